// round 6
// baseline (speedup 1.0000x reference)
#include <cuda_runtime.h>
#include <cstdint>
#include <math.h>

// AttentionBlock via mma.sync m16n8k8 tf32 (base-PTX, runs on sm_103 HMMA path).
// out = smooth_softmax((x@Wq)@(y@Wk)^T / 16) @ (y@Wv)
// Per row: out = (accE/Z + 0.1*accR) / (0.1*R + 1)
// Round 6: __expf (MUFU-bound, ~500us of EX2) replaced by FMA-only exp2 poly.

#define N_Q   16384
#define MCTX  4096
#define S_IN  256
#define D_P   256
#define KT    32                 // keys per tile
#define NT    (MCTX / KT)        // 128 tiles
#define DH    128                // output dims per CTA

// scratch (fragment-packed layouts)
__device__ float  g_Q  [N_Q * D_P];          // qgemm output, row-major, tf32-rounded
__device__ float4 g_Qf [N_Q * D_P / 4];      // [qblk][w8][s32][lane32] -> {a0,a1,a2,a3}
__device__ float  g_Kf [MCTX * D_P];         // [tile][s32][nt4][lane32][2] -> {b0,b1}
__device__ float  g_Vf [MCTX * D_P];         // [tile][h2][sp4][nt16][lane32][2]

// ---------------------------------------------------------------- helpers
__device__ __forceinline__ uint32_t smem_u32(const void* p) {
    uint32_t a;
    asm("{ .reg .u64 t; cvta.to.shared.u64 t, %1; cvt.u32.u64 %0, t; }" : "=r"(a) : "l"(p));
    return a;
}
__device__ __forceinline__ uint32_t f2tf32(float x) {
    uint32_t r; asm("cvt.rna.tf32.f32 %0, %1;" : "=r"(r) : "f"(x)); return r;
}
__device__ __forceinline__ void lds128(uint32_t r[4], uint32_t a) {
    asm volatile("ld.shared.v4.b32 {%0,%1,%2,%3}, [%4];"
        : "=r"(r[0]), "=r"(r[1]), "=r"(r[2]), "=r"(r[3]) : "r"(a));
}
__device__ __forceinline__ void lds64(uint32_t r[2], uint32_t a) {
    asm volatile("ld.shared.v2.b32 {%0,%1}, [%2];" : "=r"(r[0]), "=r"(r[1]) : "r"(a));
}
__device__ __forceinline__ void mma_tf32(float c[4], const uint32_t a[4], const uint32_t b[2]) {
    asm volatile("mma.sync.aligned.m16n8k8.row.col.f32.tf32.tf32.f32 "
        "{%0,%1,%2,%3}, {%4,%5,%6,%7}, {%8,%9}, {%0,%1,%2,%3};"
        : "+f"(c[0]), "+f"(c[1]), "+f"(c[2]), "+f"(c[3])
        : "r"(a[0]), "r"(a[1]), "r"(a[2]), "r"(a[3]), "r"(b[0]), "r"(b[1]));
}
#define CP16(dst, src) \
    asm volatile("cp.async.cg.shared.global [%0], [%1], 16;" :: "r"(dst), "l"(src))
#define CP_COMMIT() asm volatile("cp.async.commit_group;" ::: "memory")

// FMA-only exp: e = exp(s/16) = 2^t with t = s*(0.0625*log2e); also r = relu(s/16).
// Range-reduce by magic rounding; 2^f via degree-5 Taylor (rel err ~2e-6);
// scale by 2^n through exponent injection (bias 0x4B400000 << 23 == 0).
#define SCALE_L2E 0.09016844129899994f   /* 0.0625 * log2(e) */
#define LN2F      0.6931471805599453f
__device__ __forceinline__ void exp_relu(float s, float& e, float& rv) {
    float t  = s * SCALE_L2E;
    float k  = t + 12582912.f;           // rint via magic (RN)
    float nf = k - 12582912.f;
    float f  = t - nf;
    float p  = 0.00133335581464284f;
    p = fmaf(p, f, 0.00961812910762848f);
    p = fmaf(p, f, 0.0555041086648216f);
    p = fmaf(p, f, 0.240226506959101f);
    p = fmaf(p, f, 0.693147180559945f);
    p = fmaf(p, f, 1.0f);
    e  = __uint_as_float(__float_as_uint(p) + (__float_as_uint(k) << 23));
    rv = fmaxf(t, 0.f) * LN2F;           // relu(s/16) = relu(t)*ln2
}

// ---------------------------------------------------------------- K/V projection
// writes fragment-packed g_Kf / g_Vf directly (coalesced stores).
__global__ __launch_bounds__(256) void proj_kv_kernel(const float* __restrict__ y,
                                                      const float* __restrict__ Wk,
                                                      const float* __restrict__ Wv) {
    int a = blockIdx.x * blockDim.x + threadIdx.x;
    const int total = MCTX * D_P;   // 1M
    if (a < total) {
        // K frag: b=a&1, lane=(a>>1)&31, nt=(a>>6)&3, s=(a>>8)&31, tile=a>>13
        int b = a & 1, lane = (a >> 1) & 31, nt = (a >> 6) & 3, s = (a >> 8) & 31, tile = a >> 13;
        int m = tile * KT + nt * 8 + (lane >> 2);
        int p = s * 8 + (lane & 3) + 4 * b;
        float acc = 0.f;
        #pragma unroll
        for (int j = 0; j < 7; j++) acc = fmaf(y[m * 7 + j], Wk[j * D_P + p], acc);
        g_Kf[a] = __uint_as_float(f2tf32(acc));
    } else if (a < 2 * total) {
        int a2 = a - total;
        // V frag: b, lane, nt(16), sp(4), h(2), tile
        int b = a2 & 1, lane = (a2 >> 1) & 31, nt = (a2 >> 6) & 15;
        int sp = (a2 >> 10) & 3, h = (a2 >> 12) & 1, tile = a2 >> 13;
        int m = tile * KT + sp * 8 + (lane & 3) + 4 * b;
        int d = h * DH + nt * 8 + (lane >> 2);
        float acc = 0.f;
        #pragma unroll
        for (int j = 0; j < 7; j++) acc = fmaf(y[m * 7 + j], Wv[j * D_P + d], acc);
        g_Vf[a2] = __uint_as_float(f2tf32(acc));
    }
}

// ---------------------------------------------------------------- Q GEMM (fp32 SIMT)
__global__ __launch_bounds__(256) void qgemm_kernel(const float* __restrict__ A,
                                                    const float* __restrict__ B) {
    __shared__ float As[16][68];
    __shared__ float Bs[16][68];
    int m0 = blockIdx.y * 64, n0 = blockIdx.x * 64;
    int t = threadIdx.x, tm = t >> 4, tn = t & 15;
    float acc[4][4] = {};
    for (int k0 = 0; k0 < S_IN; k0 += 16) {
        {
            int ar = t >> 2, ak = (t & 3) << 2;
            float4 av = *(const float4*)&A[(m0 + ar) * S_IN + k0 + ak];
            As[ak + 0][ar] = av.x; As[ak + 1][ar] = av.y;
            As[ak + 2][ar] = av.z; As[ak + 3][ar] = av.w;
        }
        {
            int br = t >> 4, bn = (t & 15) << 2;
            *(float4*)&Bs[br][bn] = *(const float4*)&B[(k0 + br) * D_P + n0 + bn];
        }
        __syncthreads();
        #pragma unroll
        for (int k = 0; k < 16; k++) {
            float4 a4 = *(const float4*)&As[k][tm << 2];
            float4 b4 = *(const float4*)&Bs[k][tn << 2];
            float av_[4] = {a4.x, a4.y, a4.z, a4.w};
            float bv_[4] = {b4.x, b4.y, b4.z, b4.w};
            #pragma unroll
            for (int i = 0; i < 4; i++)
                #pragma unroll
                for (int j = 0; j < 4; j++)
                    acc[i][j] = fmaf(av_[i], bv_[j], acc[i][j]);
        }
        __syncthreads();
    }
    #pragma unroll
    for (int i = 0; i < 4; i++) {
        float4 o = make_float4(__uint_as_float(f2tf32(acc[i][0])),
                               __uint_as_float(f2tf32(acc[i][1])),
                               __uint_as_float(f2tf32(acc[i][2])),
                               __uint_as_float(f2tf32(acc[i][3])));
        *(float4*)&g_Q[(size_t)(m0 + (tm << 2) + i) * D_P + n0 + (tn << 2)] = o;
    }
}

// ---------------------------------------------------------------- Q repack (row-major -> A frags)
__global__ __launch_bounds__(256) void qrepack_kernel() {
    int u = blockIdx.x * 256 + threadIdx.x;       // one float4 per thread, 1M total
    int lane = u & 31, s = (u >> 5) & 31, w = (u >> 10) & 7, qb = u >> 13;
    int r = qb * 128 + w * 16 + (lane >> 2);
    int c = s * 8 + (lane & 3);
    float4 v = make_float4(g_Q[(size_t)r * D_P + c],
                           g_Q[(size_t)(r + 8) * D_P + c],
                           g_Q[(size_t)r * D_P + c + 4],
                           g_Q[(size_t)(r + 8) * D_P + c + 4]);
    g_Qf[u] = v;
}

// ---------------------------------------------------------------- fused attention
// SMEM: Qf 128K | Kf 2x32K | Vf 2x16K = 224K
#define QS_BYTES  131072
#define KS_BYTES  32768
#define VS_BYTES  16384
#define ATT_SMEM  (QS_BYTES + 2 * KS_BYTES + 2 * VS_BYTES)

__global__ __launch_bounds__(256, 1) void attn_kernel(float* __restrict__ out) {
    extern __shared__ char smem[];
    const uint32_t sb = smem_u32(smem);
    const uint32_t QS = sb, KS = sb + QS_BYTES, VS = KS + 2 * KS_BYTES;

    const int t    = threadIdx.x;
    const int w    = t >> 5;
    const int lane = t & 31;
    const int g    = lane >> 2;
    const int q    = lane & 3;
    const int qblk = blockIdx.x;
    const int h    = blockIdx.y;
    const int q0   = qblk * 128;
    const int dh0  = h * DH;

    // ---- prologue: Q + tile0 K/V ----
    {
        const float* qsrc = (const float*)(g_Qf + (size_t)qblk * 8192);
        #pragma unroll
        for (int i = 0; i < 32; i++) {
            int f = t + (i << 8);
            CP16(QS + f * 16, qsrc + f * 4);
        }
        const float* ksrc = g_Kf;
        #pragma unroll
        for (int i = 0; i < 8; i++) {
            int f = t + (i << 8);
            CP16(KS + f * 16, ksrc + f * 4);
        }
        const float* vsrc = g_Vf + (size_t)h * 4096;
        #pragma unroll
        for (int i = 0; i < 4; i++) {
            int f = t + (i << 8);
            CP16(VS + f * 16, vsrc + f * 4);
        }
        CP_COMMIT();
    }

    float accE[16][4], accR[16][4];
    #pragma unroll
    for (int n = 0; n < 16; n++)
        #pragma unroll
        for (int i = 0; i < 4; i++) { accE[n][i] = 0.f; accR[n][i] = 0.f; }
    float zg = 0.f, zg8 = 0.f, rg = 0.f, rg8 = 0.f;

    const int srcq = (lane & ~3) + (q >> 1);
    const int srcq2 = srcq + 2;
    const int qodd = q & 1;

    for (int tile = 0; tile < NT; tile++) {
        // prefetch next K/V
        if (tile + 1 < NT) {
            uint32_t KSn = KS + ((tile + 1) & 1) * KS_BYTES;
            uint32_t VSn = VS + ((tile + 1) & 1) * VS_BYTES;
            const float* ksrc = g_Kf + (size_t)(tile + 1) * 8192;
            const float* vsrc = g_Vf + ((size_t)(tile + 1) * 2 + h) * 4096;
            #pragma unroll
            for (int i = 0; i < 8; i++) {
                int f = t + (i << 8);
                CP16(KSn + f * 16, ksrc + f * 4);
            }
            #pragma unroll
            for (int i = 0; i < 4; i++) {
                int f = t + (i << 8);
                CP16(VSn + f * 16, vsrc + f * 4);
            }
            CP_COMMIT();
            asm volatile("cp.async.wait_group 1;" ::: "memory");
        } else {
            asm volatile("cp.async.wait_group 0;" ::: "memory");
        }
        __syncthreads();

        const uint32_t KSb = KS + (tile & 1) * KS_BYTES;
        const uint32_t VSb = VS + (tile & 1) * VS_BYTES;

        // ---- S = Q @ K^T : 16q x 32keys per warp ----
        float sc[4][4];
        #pragma unroll
        for (int n = 0; n < 4; n++)
            #pragma unroll
            for (int i = 0; i < 4; i++) sc[n][i] = 0.f;

        #pragma unroll 8
        for (int s = 0; s < 32; s++) {
            uint32_t a[4];
            lds128(a, QS + (uint32_t)(w * 1024 + s * 32 + lane) * 16);
            #pragma unroll
            for (int nt = 0; nt < 4; nt++) {
                uint32_t b[2];
                lds64(b, KSb + (uint32_t)(s * 256 + nt * 64 + lane * 2) * 4);
                mma_tf32(sc[nt], a, b);
            }
        }

        // ---- per 8-key group: weights (FMA exp), row sums, PV mma ----
        #pragma unroll
        for (int sp = 0; sp < 4; sp++) {
            uint32_t ef[4], rf[4];
            #pragma unroll
            for (int i = 0; i < 4; i++) {
                float e, rv;
                exp_relu(sc[sp][i], e, rv);
                ef[i] = f2tf32(e);
                rf[i] = f2tf32(rv);
                float ev = __uint_as_float(ef[i]);
                float rr = __uint_as_float(rf[i]);
                if (i < 2) { zg += ev; rg += rr; } else { zg8 += ev; rg8 += rr; }
            }
            // C-layout -> A-layout permute (quad shuffles)
            uint32_t aE[4], aR[4];
            {
                uint32_t x0 = __shfl_sync(0xffffffffu, ef[0], srcq);
                uint32_t x1 = __shfl_sync(0xffffffffu, ef[1], srcq);
                aE[0] = qodd ? x1 : x0;
                uint32_t x2 = __shfl_sync(0xffffffffu, ef[2], srcq);
                uint32_t x3 = __shfl_sync(0xffffffffu, ef[3], srcq);
                aE[1] = qodd ? x3 : x2;
                uint32_t y0 = __shfl_sync(0xffffffffu, ef[0], srcq2);
                uint32_t y1 = __shfl_sync(0xffffffffu, ef[1], srcq2);
                aE[2] = qodd ? y1 : y0;
                uint32_t y2 = __shfl_sync(0xffffffffu, ef[2], srcq2);
                uint32_t y3 = __shfl_sync(0xffffffffu, ef[3], srcq2);
                aE[3] = qodd ? y3 : y2;
            }
            {
                uint32_t x0 = __shfl_sync(0xffffffffu, rf[0], srcq);
                uint32_t x1 = __shfl_sync(0xffffffffu, rf[1], srcq);
                aR[0] = qodd ? x1 : x0;
                uint32_t x2 = __shfl_sync(0xffffffffu, rf[2], srcq);
                uint32_t x3 = __shfl_sync(0xffffffffu, rf[3], srcq);
                aR[1] = qodd ? x3 : x2;
                uint32_t y0 = __shfl_sync(0xffffffffu, rf[0], srcq2);
                uint32_t y1 = __shfl_sync(0xffffffffu, rf[1], srcq2);
                aR[2] = qodd ? y1 : y0;
                uint32_t y2 = __shfl_sync(0xffffffffu, rf[2], srcq2);
                uint32_t y3 = __shfl_sync(0xffffffffu, rf[3], srcq2);
                aR[3] = qodd ? y3 : y2;
            }
            #pragma unroll
            for (int nt = 0; nt < 16; nt++) {
                uint32_t b[2];
                lds64(b, VSb + (uint32_t)(sp * 1024 + nt * 64 + lane * 2) * 4);
                mma_tf32(accE[nt], aE, b);
                mma_tf32(accR[nt], aR, b);
            }
        }
        __syncthreads();
    }

    // ---- epilogue: quad-reduce row sums, normalize, store ----
    zg  += __shfl_xor_sync(0xffffffffu, zg, 1);
    zg  += __shfl_xor_sync(0xffffffffu, zg, 2);
    zg8 += __shfl_xor_sync(0xffffffffu, zg8, 1);
    zg8 += __shfl_xor_sync(0xffffffffu, zg8, 2);
    rg  += __shfl_xor_sync(0xffffffffu, rg, 1);
    rg  += __shfl_xor_sync(0xffffffffu, rg, 2);
    rg8 += __shfl_xor_sync(0xffffffffu, rg8, 1);
    rg8 += __shfl_xor_sync(0xffffffffu, rg8, 2);

    const float iz0 = 1.f / zg;
    const float iz1 = 1.f / zg8;
    const float dn0 = 1.f / fmaf(0.1f, rg, 1.f);
    const float dn1 = 1.f / fmaf(0.1f, rg8, 1.f);

    const int r0 = q0 + w * 16 + g;
    #pragma unroll
    for (int nt = 0; nt < 16; nt++) {
        int col = dh0 + nt * 8 + 2 * q;
        float2 o0, o1;
        o0.x = fmaf(accE[nt][0], iz0, 0.1f * accR[nt][0]) * dn0;
        o0.y = fmaf(accE[nt][1], iz0, 0.1f * accR[nt][1]) * dn0;
        o1.x = fmaf(accE[nt][2], iz1, 0.1f * accR[nt][2]) * dn1;
        o1.y = fmaf(accE[nt][3], iz1, 0.1f * accR[nt][3]) * dn1;
        *(float2*)&out[(size_t)r0 * D_P + col]       = o0;
        *(float2*)&out[(size_t)(r0 + 8) * D_P + col] = o1;
    }
}

// ---------------------------------------------------------------------------
extern "C" void kernel_launch(void* const* d_in, const int* in_sizes, int n_in,
                              void* d_out, int out_size) {
    const float* x  = (const float*)d_in[0];
    const float* y  = (const float*)d_in[1];
    const float* Wq = (const float*)d_in[2];
    const float* Wk = (const float*)d_in[3];
    const float* Wv = (const float*)d_in[4];
    float* out = (float*)d_out;

    cudaFuncSetAttribute(attn_kernel, cudaFuncAttributeMaxDynamicSharedMemorySize,
                         ATT_SMEM);

    proj_kv_kernel<<<(2 * MCTX * D_P + 255) / 256, 256>>>(y, Wk, Wv);
    qgemm_kernel<<<dim3(D_P / 64, N_Q / 64), 256>>>(x, Wq);
    qrepack_kernel<<<(N_Q * D_P / 4) / 256, 256>>>();
    attn_kernel<<<dim3(N_Q / 128, 2), 256, ATT_SMEM>>>(out);
}

// round 7
// speedup vs baseline: 1.7831x; 1.7831x over previous
#include <cuda_runtime.h>
#include <cuda_fp16.h>
#include <cstdint>
#include <math.h>

// AttentionBlock via mma.sync m16n8k16 fp16 (base-PTX HMMA on sm_103).
// out = smooth_softmax((x@Wq)@(y@Wk)^T / 16) @ (y@Wv)
// Per row: out = (accE/Z + 0.1*accR) / (0.1*R + 1)
// Round 7: tf32 k8 -> fp16 k16 (same 10-bit mantissa): halves HMMA count,
// halves smem bytes, and kills the C->A shuffle permute (layouts now align).

#define N_Q   16384
#define MCTX  4096
#define S_IN  256
#define D_P   256
#define KT    32                 // keys per tile
#define NT    (MCTX / KT)        // 128 tiles
#define DH    128                // output dims per CTA

// scratch
__device__ float    g_Q  [N_Q * D_P];        // qgemm output, fp32 row-major
__device__ uint4    g_Qf [N_Q * D_P / 8];    // A-frags: [qblk][w8][ks16][lane32] = a0..a3 (half2 each)
__device__ uint32_t g_Kf [MCTX * D_P / 2];   // B-frags: [tile][ks16][nt4][lane32][r2]
__device__ uint32_t g_Vf [MCTX * D_P / 2];   // B-frags: [tile][h2][ksV2][ntV16][lane32][r2]

// ---------------------------------------------------------------- helpers
__device__ __forceinline__ uint32_t smem_u32(const void* p) {
    uint32_t a;
    asm("{ .reg .u64 t; cvta.to.shared.u64 t, %1; cvt.u32.u64 %0, t; }" : "=r"(a) : "l"(p));
    return a;
}
__device__ __forceinline__ uint32_t packh2(float lo, float hi) {
    __half2 h = __floats2half2_rn(lo, hi);
    return *(uint32_t*)&h;
}
__device__ __forceinline__ void lds128(uint32_t r[4], uint32_t a) {
    asm volatile("ld.shared.v4.b32 {%0,%1,%2,%3}, [%4];"
        : "=r"(r[0]), "=r"(r[1]), "=r"(r[2]), "=r"(r[3]) : "r"(a));
}
__device__ __forceinline__ void lds64(uint32_t r[2], uint32_t a) {
    asm volatile("ld.shared.v2.b32 {%0,%1}, [%2];" : "=r"(r[0]), "=r"(r[1]) : "r"(a));
}
__device__ __forceinline__ void mma_f16(float c[4], const uint32_t a[4], const uint32_t b[2]) {
    asm volatile("mma.sync.aligned.m16n8k16.row.col.f32.f16.f16.f32 "
        "{%0,%1,%2,%3}, {%4,%5,%6,%7}, {%8,%9}, {%0,%1,%2,%3};"
        : "+f"(c[0]), "+f"(c[1]), "+f"(c[2]), "+f"(c[3])
        : "r"(a[0]), "r"(a[1]), "r"(a[2]), "r"(a[3]), "r"(b[0]), "r"(b[1]));
}
#define CP16(dst, src) \
    asm volatile("cp.async.cg.shared.global [%0], [%1], 16;" :: "r"(dst), "l"(src))
#define CP_COMMIT() asm volatile("cp.async.commit_group;" ::: "memory")

// FMA-only exp (validated round 6): e = exp(s/16) = 2^t, t = s*0.0625*log2e;
// r = relu(s/16) = relu(t)*ln2.
#define SCALE_L2E 0.09016844129899994f
#define LN2F      0.6931471805599453f
__device__ __forceinline__ void exp_relu(float s, float& e, float& rv) {
    float t  = s * SCALE_L2E;
    float k  = t + 12582912.f;
    float nf = k - 12582912.f;
    float f  = t - nf;
    float p  = 0.00133335581464284f;
    p = fmaf(p, f, 0.00961812910762848f);
    p = fmaf(p, f, 0.0555041086648216f);
    p = fmaf(p, f, 0.240226506959101f);
    p = fmaf(p, f, 0.693147180559945f);
    p = fmaf(p, f, 1.0f);
    e  = __uint_as_float(__float_as_uint(p) + (__float_as_uint(k) << 23));
    rv = fmaxf(t, 0.f) * LN2F;
}

// ---------------------------------------------------------------- K/V projection
// Writes fp16 B-fragment-packed g_Kf / g_Vf directly. One u32 (2 halves) per thread.
__global__ __launch_bounds__(256) void proj_kv_kernel(const float* __restrict__ y,
                                                      const float* __restrict__ Wk,
                                                      const float* __restrict__ Wv) {
    int a = blockIdx.x * blockDim.x + threadIdx.x;
    const int totalK = MCTX * D_P / 2;   // 524288 u32
    if (a < totalK) {
        // [tile][ks16][nt4][lane32][r2]
        int r = a & 1, lane = (a >> 1) & 31, nt = (a >> 6) & 3, ks = (a >> 8) & 15, tile = a >> 12;
        int g = lane >> 2, q = lane & 3;
        int m = tile * KT + nt * 8 + g;          // key index
        int p = ks * 16 + r * 8 + 2 * q;         // proj dim (lo), +1 (hi)
        float v0 = 0.f, v1 = 0.f;
        #pragma unroll
        for (int j = 0; j < 7; j++) {
            float yy = y[m * 7 + j];
            v0 = fmaf(yy, Wk[j * D_P + p], v0);
            v1 = fmaf(yy, Wk[j * D_P + p + 1], v1);
        }
        g_Kf[a] = packh2(v0, v1);
    } else if (a < 2 * totalK) {
        int a2 = a - totalK;
        // [tile][h2][ksV2][ntV16][lane32][r2]
        int r = a2 & 1, lane = (a2 >> 1) & 31, ntV = (a2 >> 6) & 15;
        int ksV = (a2 >> 10) & 1, h = (a2 >> 11) & 1, tile = a2 >> 12;
        int g = lane >> 2, q = lane & 3;
        int m = tile * KT + ksV * 16 + r * 8 + 2 * q;   // key (lo), +1 (hi)
        int d = h * DH + ntV * 8 + g;                   // output dim
        float v0 = 0.f, v1 = 0.f;
        #pragma unroll
        for (int j = 0; j < 7; j++) {
            float w0 = Wv[j * D_P + d];
            v0 = fmaf(y[m * 7 + j],       w0, v0);
            v1 = fmaf(y[(m + 1) * 7 + j], w0, v1);
        }
        g_Vf[a2] = packh2(v0, v1);
    }
}

// ---------------------------------------------------------------- Q GEMM (fp32 SIMT)
__global__ __launch_bounds__(256) void qgemm_kernel(const float* __restrict__ A,
                                                    const float* __restrict__ B) {
    __shared__ float As[16][68];
    __shared__ float Bs[16][68];
    int m0 = blockIdx.y * 64, n0 = blockIdx.x * 64;
    int t = threadIdx.x, tm = t >> 4, tn = t & 15;
    float acc[4][4] = {};
    for (int k0 = 0; k0 < S_IN; k0 += 16) {
        {
            int ar = t >> 2, ak = (t & 3) << 2;
            float4 av = *(const float4*)&A[(m0 + ar) * S_IN + k0 + ak];
            As[ak + 0][ar] = av.x; As[ak + 1][ar] = av.y;
            As[ak + 2][ar] = av.z; As[ak + 3][ar] = av.w;
        }
        {
            int br = t >> 4, bn = (t & 15) << 2;
            *(float4*)&Bs[br][bn] = *(const float4*)&B[(k0 + br) * D_P + n0 + bn];
        }
        __syncthreads();
        #pragma unroll
        for (int k = 0; k < 16; k++) {
            float4 a4 = *(const float4*)&As[k][tm << 2];
            float4 b4 = *(const float4*)&Bs[k][tn << 2];
            float av_[4] = {a4.x, a4.y, a4.z, a4.w};
            float bv_[4] = {b4.x, b4.y, b4.z, b4.w};
            #pragma unroll
            for (int i = 0; i < 4; i++)
                #pragma unroll
                for (int j = 0; j < 4; j++)
                    acc[i][j] = fmaf(av_[i], bv_[j], acc[i][j]);
        }
        __syncthreads();
    }
    #pragma unroll
    for (int i = 0; i < 4; i++) {
        float4 o = make_float4(acc[i][0], acc[i][1], acc[i][2], acc[i][3]);
        *(float4*)&g_Q[(size_t)(m0 + (tm << 2) + i) * D_P + n0 + (tn << 2)] = o;
    }
}

// ---------------------------------------------------------------- Q repack -> fp16 A frags
__global__ __launch_bounds__(256) void qrepack_kernel() {
    int u = blockIdx.x * 256 + threadIdx.x;       // one uint4 per thread, 524288 total
    int lane = u & 31, ks = (u >> 5) & 15, w = (u >> 9) & 7, qb = u >> 12;
    int row = qb * 128 + w * 16 + (lane >> 2);
    int c0  = ks * 16 + 2 * (lane & 3);
    const float* Qr0 = &g_Q[(size_t)row * D_P];
    const float* Qr8 = &g_Q[(size_t)(row + 8) * D_P];
    uint4 v;
    v.x = packh2(Qr0[c0],     Qr0[c0 + 1]);      // a0: row g,   k 2q,2q+1
    v.y = packh2(Qr8[c0],     Qr8[c0 + 1]);      // a1: row g+8
    v.z = packh2(Qr0[c0 + 8], Qr0[c0 + 9]);      // a2: row g,   k +8
    v.w = packh2(Qr8[c0 + 8], Qr8[c0 + 9]);      // a3: row g+8, k +8
    g_Qf[u] = v;
}

// ---------------------------------------------------------------- fused attention
// SMEM: Qf 64K | Kf 2x16K | Vf 2x8K = 112K
#define QS_BYTES  65536
#define KS_BYTES  16384
#define VS_BYTES  8192
#define ATT_SMEM  (QS_BYTES + 2 * KS_BYTES + 2 * VS_BYTES)

__global__ __launch_bounds__(256, 1) void attn_kernel(float* __restrict__ out) {
    extern __shared__ char smem[];
    const uint32_t sb = smem_u32(smem);
    const uint32_t QS = sb, KS = sb + QS_BYTES, VS = KS + 2 * KS_BYTES;

    const int t    = threadIdx.x;
    const int w    = t >> 5;
    const int lane = t & 31;
    const int g    = lane >> 2;
    const int q    = lane & 3;
    const int qblk = blockIdx.x;
    const int h    = blockIdx.y;
    const int q0   = qblk * 128;
    const int dh0  = h * DH;

    // ---- prologue: Q frags + tile0 K/V ----
    {
        const uint4* qsrc = g_Qf + (size_t)qblk * 4096;
        #pragma unroll
        for (int i = 0; i < 16; i++) {
            int f = t + (i << 8);
            CP16(QS + f * 16, qsrc + f);
        }
        const uint32_t* ksrc = g_Kf;                      // tile 0
        #pragma unroll
        for (int i = 0; i < 4; i++) {
            int f = t + (i << 8);
            CP16(KS + f * 16, ksrc + f * 4);
        }
        const uint32_t* vsrc = g_Vf + (size_t)h * 2048;   // tile 0, half h
        #pragma unroll
        for (int i = 0; i < 2; i++) {
            int f = t + (i << 8);
            CP16(VS + f * 16, vsrc + f * 4);
        }
        CP_COMMIT();
    }

    float accE[16][4], accR[16][4];
    #pragma unroll
    for (int n = 0; n < 16; n++)
        #pragma unroll
        for (int i = 0; i < 4; i++) { accE[n][i] = 0.f; accR[n][i] = 0.f; }
    float zg = 0.f, zg8 = 0.f, rg = 0.f, rg8 = 0.f;

    for (int tile = 0; tile < NT; tile++) {
        // prefetch next K/V
        if (tile + 1 < NT) {
            uint32_t KSn = KS + ((tile + 1) & 1) * KS_BYTES;
            uint32_t VSn = VS + ((tile + 1) & 1) * VS_BYTES;
            const uint32_t* ksrc = g_Kf + (size_t)(tile + 1) * 4096;
            const uint32_t* vsrc = g_Vf + ((size_t)(tile + 1) * 2 + h) * 2048;
            #pragma unroll
            for (int i = 0; i < 4; i++) {
                int f = t + (i << 8);
                CP16(KSn + f * 16, ksrc + f * 4);
            }
            #pragma unroll
            for (int i = 0; i < 2; i++) {
                int f = t + (i << 8);
                CP16(VSn + f * 16, vsrc + f * 4);
            }
            CP_COMMIT();
            asm volatile("cp.async.wait_group 1;" ::: "memory");
        } else {
            asm volatile("cp.async.wait_group 0;" ::: "memory");
        }
        __syncthreads();

        const uint32_t KSb = KS + (tile & 1) * KS_BYTES;
        const uint32_t VSb = VS + (tile & 1) * VS_BYTES;

        // ---- S = Q @ K^T : 16q x 32keys per warp, K=256 -> 16 ksteps ----
        float sc[4][4];
        #pragma unroll
        for (int n = 0; n < 4; n++)
            #pragma unroll
            for (int i = 0; i < 4; i++) sc[n][i] = 0.f;

        #pragma unroll 4
        for (int ks = 0; ks < 16; ks++) {
            uint32_t a[4];
            lds128(a, QS + (uint32_t)((w * 16 + ks) * 32 + lane) * 16);
            #pragma unroll
            for (int nt = 0; nt < 4; nt++) {
                uint32_t b[2];
                lds64(b, KSb + (uint32_t)((ks * 4 + nt) * 32 + lane) * 8);
                mma_f16(sc[nt], a, b);
            }
        }

        // ---- convert: e/r weights, row sums; pack into PV A-frags (no shuffles) ----
        uint32_t eh[4][2], rh[4][2];
        #pragma unroll
        for (int nt = 0; nt < 4; nt++) {
            float e0, e1, e2, e3, r0, r1, r2, r3;
            exp_relu(sc[nt][0], e0, r0);
            exp_relu(sc[nt][1], e1, r1);
            exp_relu(sc[nt][2], e2, r2);
            exp_relu(sc[nt][3], e3, r3);
            eh[nt][0] = packh2(e0, e1);   // row g,   keys 2q,2q+1
            eh[nt][1] = packh2(e2, e3);   // row g+8
            rh[nt][0] = packh2(r0, r1);
            rh[nt][1] = packh2(r2, r3);
            zg  += e0 + e1;  zg8 += e2 + e3;
            rg  += r0 + r1;  rg8 += r2 + r3;
        }

        // ---- PV: accE += E@V, accR += R@V : 2 ksteps x 16 ntV ----
        #pragma unroll
        for (int ksV = 0; ksV < 2; ksV++) {
            uint32_t aE[4] = { eh[2 * ksV][0], eh[2 * ksV][1],
                               eh[2 * ksV + 1][0], eh[2 * ksV + 1][1] };
            uint32_t aR[4] = { rh[2 * ksV][0], rh[2 * ksV][1],
                               rh[2 * ksV + 1][0], rh[2 * ksV + 1][1] };
            #pragma unroll
            for (int ntV = 0; ntV < 16; ntV++) {
                uint32_t b[2];
                lds64(b, VSb + (uint32_t)((ksV * 16 + ntV) * 32 + lane) * 8);
                mma_f16(accE[ntV], aE, b);
                mma_f16(accR[ntV], aR, b);
            }
        }
        __syncthreads();
    }

    // ---- epilogue: quad-reduce row sums, normalize, store ----
    zg  += __shfl_xor_sync(0xffffffffu, zg, 1);
    zg  += __shfl_xor_sync(0xffffffffu, zg, 2);
    zg8 += __shfl_xor_sync(0xffffffffu, zg8, 1);
    zg8 += __shfl_xor_sync(0xffffffffu, zg8, 2);
    rg  += __shfl_xor_sync(0xffffffffu, rg, 1);
    rg  += __shfl_xor_sync(0xffffffffu, rg, 2);
    rg8 += __shfl_xor_sync(0xffffffffu, rg8, 1);
    rg8 += __shfl_xor_sync(0xffffffffu, rg8, 2);

    const float iz0 = 1.f / zg;
    const float iz1 = 1.f / zg8;
    const float dn0 = 1.f / fmaf(0.1f, rg, 1.f);
    const float dn1 = 1.f / fmaf(0.1f, rg8, 1.f);

    const int r0 = q0 + w * 16 + g;
    #pragma unroll
    for (int nt = 0; nt < 16; nt++) {
        int col = dh0 + nt * 8 + 2 * q;
        float2 o0, o1;
        o0.x = fmaf(accE[nt][0], iz0, 0.1f * accR[nt][0]) * dn0;
        o0.y = fmaf(accE[nt][1], iz0, 0.1f * accR[nt][1]) * dn0;
        o1.x = fmaf(accE[nt][2], iz1, 0.1f * accR[nt][2]) * dn1;
        o1.y = fmaf(accE[nt][3], iz1, 0.1f * accR[nt][3]) * dn1;
        *(float2*)&out[(size_t)r0 * D_P + col]       = o0;
        *(float2*)&out[(size_t)(r0 + 8) * D_P + col] = o1;
    }
}

// ---------------------------------------------------------------------------
extern "C" void kernel_launch(void* const* d_in, const int* in_sizes, int n_in,
                              void* d_out, int out_size) {
    const float* x  = (const float*)d_in[0];
    const float* y  = (const float*)d_in[1];
    const float* Wq = (const float*)d_in[2];
    const float* Wk = (const float*)d_in[3];
    const float* Wv = (const float*)d_in[4];
    float* out = (float*)d_out;

    cudaFuncSetAttribute(attn_kernel, cudaFuncAttributeMaxDynamicSharedMemorySize,
                         ATT_SMEM);

    proj_kv_kernel<<<(MCTX * D_P) / 256, 256>>>(y, Wk, Wv);   // 2*524288 threads
    qgemm_kernel<<<dim3(D_P / 64, N_Q / 64), 256>>>(x, Wq);
    qrepack_kernel<<<(N_Q * D_P / 8) / 256, 256>>>();
    attn_kernel<<<dim3(N_Q / 128, 2), 256, ATT_SMEM>>>(out);
}

// round 9
// speedup vs baseline: 8.7736x; 4.9203x over previous
#include <cuda_runtime.h>
#include <cuda_fp16.h>
#include <cstdint>
#include <math.h>

// AttentionBlock, rank-7 factored form.
// S = (x·Wq·Wk^T/16)·y^T  (K-dim 7!), accEy = E·y, accRy = R·y (N-dim 7!),
// out = ((accEy/Z + 0.1·accRy)/(0.1R+1)) · Wv.
// HMMA m16n8k8/k16 fp16 (fragment conventions validated in round 7).

#define N_Q   16384
#define MCTX  4096
#define S_IN  256
#define D_P   256
#define KSPLIT 2
#define KEYS_PER (MCTX / KSPLIT)   // 2048
#define TILES (KEYS_PER / 32)      // 64

// scratch
__device__ float    g_Wqk[S_IN * 8];             // Wq@Wk^T/16, [256][8] (col7=0)
__device__ uint2    g_QKf [(N_Q / 16) * 32];     // QKp A-frags (k8): [qgroup][lane]
__device__ uint32_t g_ySf [(MCTX / 8) * 32];     // y^T B-frags (k8, S):  [grp][lane]
__device__ uint32_t g_yPf [(MCTX / 16) * 64];    // y B-frags (k16, PV): [ks][lane][r]
__device__ float    g_pE  [KSPLIT * N_Q * 8];    // partial accEy
__device__ float    g_pR  [KSPLIT * N_Q * 8];    // partial accRy
__device__ float    g_pZ  [KSPLIT * N_Q];        // partial Z
__device__ float    g_pS  [KSPLIT * N_Q];        // partial R-sum

// ---------------------------------------------------------------- helpers
__device__ __forceinline__ uint32_t smem_u32(const void* p) {
    uint32_t a;
    asm("{ .reg .u64 t; cvta.to.shared.u64 t, %1; cvt.u32.u64 %0, t; }" : "=r"(a) : "l"(p));
    return a;
}
__device__ __forceinline__ uint32_t packh2(float lo, float hi) {
    __half2 h = __floats2half2_rn(lo, hi);
    return *(uint32_t*)&h;
}
__device__ __forceinline__ void lds32(uint32_t& r, uint32_t a) {
    asm volatile("ld.shared.b32 %0, [%1];" : "=r"(r) : "r"(a));
}
__device__ __forceinline__ void lds64(uint32_t r[2], uint32_t a) {
    asm volatile("ld.shared.v2.b32 {%0,%1}, [%2];" : "=r"(r[0]), "=r"(r[1]) : "r"(a));
}
__device__ __forceinline__ void mma_f16_k8(float c[4], const uint32_t a[2], uint32_t b) {
    asm volatile("mma.sync.aligned.m16n8k8.row.col.f32.f16.f16.f32 "
        "{%0,%1,%2,%3}, {%4,%5}, {%6}, {%0,%1,%2,%3};"
        : "+f"(c[0]), "+f"(c[1]), "+f"(c[2]), "+f"(c[3])
        : "r"(a[0]), "r"(a[1]), "r"(b));
}
__device__ __forceinline__ void mma_f16(float c[4], const uint32_t a[4], const uint32_t b[2]) {
    asm volatile("mma.sync.aligned.m16n8k16.row.col.f32.f16.f16.f32 "
        "{%0,%1,%2,%3}, {%4,%5,%6,%7}, {%8,%9}, {%0,%1,%2,%3};"
        : "+f"(c[0]), "+f"(c[1]), "+f"(c[2]), "+f"(c[3])
        : "r"(a[0]), "r"(a[1]), "r"(a[2]), "r"(a[3]), "r"(b[0]), "r"(b[1]));
}
#define CP16(dst, src) \
    asm volatile("cp.async.cg.shared.global [%0], [%1], 16;" :: "r"(dst), "l"(src))
#define CP_COMMIT() asm volatile("cp.async.commit_group;" ::: "memory")
#define CP_WAIT0()  asm volatile("cp.async.wait_group 0;" ::: "memory")

// FMA-only exp on the (already /16-scaled) score s: e = exp(s) = 2^(s*log2e).
#define L2E   1.4426950408889634f
#define LN2F  0.6931471805599453f
__device__ __forceinline__ void exp_relu(float s, float& e, float& rv) {
    float t  = s * L2E;
    float k  = t + 12582912.f;
    float nf = k - 12582912.f;
    float f  = t - nf;
    float p  = 0.00133335581464284f;
    p = fmaf(p, f, 0.00961812910762848f);
    p = fmaf(p, f, 0.0555041086648216f);
    p = fmaf(p, f, 0.240226506959101f);
    p = fmaf(p, f, 0.693147180559945f);
    p = fmaf(p, f, 1.0f);
    e  = __uint_as_float(__float_as_uint(p) + (__float_as_uint(k) << 23));
    rv = fmaxf(t, 0.f) * LN2F;
}

// ---------------------------------------------------------------- Wqk = Wq@Wk^T/16
__global__ __launch_bounds__(256) void wqk_kernel(const float* __restrict__ Wq,
                                                  const float* __restrict__ Wk) {
    __shared__ float wks[7 * 256];
    int t = threadIdx.x;
    for (int i = t; i < 7 * 256; i += 256) wks[i] = Wk[i];
    __syncthreads();
    float acc[7] = {};
    for (int p = 0; p < 256; p++) {
        float wq = Wq[t * 256 + p];
        #pragma unroll
        for (int j = 0; j < 7; j++) acc[j] = fmaf(wq, wks[j * 256 + p], acc[j]);
    }
    #pragma unroll
    for (int j = 0; j < 7; j++) g_Wqk[t * 8 + j] = acc[j] * 0.0625f;
    g_Wqk[t * 8 + 7] = 0.f;
}

// ---------------------------------------------------------------- QKp = x@Wqk -> A-frags
__global__ __launch_bounds__(256) void qkp_kernel(const float* __restrict__ x) {
    __shared__ float wqs[2048];
    int t = threadIdx.x;
    for (int i = t; i < 2048; i += 256) wqs[i] = g_Wqk[i];
    __syncthreads();
    int u = blockIdx.x * 256 + t;       // 32768 threads
    int lane = u & 31, qg = u >> 5;
    int g = lane >> 2, q = lane & 3;
    int r0 = qg * 16 + g, r1 = r0 + 8;
    int c0 = 2 * q, c1 = c0 + 1;
    float a00 = 0, a01 = 0, a10 = 0, a11 = 0;
    const float4* x0 = (const float4*)(x + (size_t)r0 * 256);
    const float4* x1 = (const float4*)(x + (size_t)r1 * 256);
    #pragma unroll 4
    for (int k4 = 0; k4 < 64; k4++) {
        float4 v0 = x0[k4], v1 = x1[k4];
        const float* ww = &wqs[k4 * 32];
        a00 = fmaf(v0.x, ww[c0], a00);       a01 = fmaf(v0.x, ww[c1], a01);
        a10 = fmaf(v1.x, ww[c0], a10);       a11 = fmaf(v1.x, ww[c1], a11);
        a00 = fmaf(v0.y, ww[8 + c0], a00);   a01 = fmaf(v0.y, ww[8 + c1], a01);
        a10 = fmaf(v1.y, ww[8 + c0], a10);   a11 = fmaf(v1.y, ww[8 + c1], a11);
        a00 = fmaf(v0.z, ww[16 + c0], a00);  a01 = fmaf(v0.z, ww[16 + c1], a01);
        a10 = fmaf(v1.z, ww[16 + c0], a10);  a11 = fmaf(v1.z, ww[16 + c1], a11);
        a00 = fmaf(v0.w, ww[24 + c0], a00);  a01 = fmaf(v0.w, ww[24 + c1], a01);
        a10 = fmaf(v1.w, ww[24 + c0], a10);  a11 = fmaf(v1.w, ww[24 + c1], a11);
    }
    uint2 o;
    o.x = packh2(a00, a01);   // row g,   cols 2q,2q+1
    o.y = packh2(a10, a11);   // row g+8
    g_QKf[u] = o;
}

// ---------------------------------------------------------------- y -> B-frags
__global__ __launch_bounds__(256) void ypack_kernel(const float* __restrict__ y) {
    int u = blockIdx.x * 256 + threadIdx.x;    // 32768
    if (u < 16384) {
        // S B-frag (k8): b = half2(y[n][2q], y[n][2q+1]), n = grp*8+g
        int lane = u & 31, grp = u >> 5;
        int g = lane >> 2, q = lane & 3;
        int n = grp * 8 + g;
        float v0 = (2 * q     < 7) ? y[n * 7 + 2 * q]     : 0.f;
        float v1 = (2 * q + 1 < 7) ? y[n * 7 + 2 * q + 1] : 0.f;
        g_ySf[u] = packh2(v0, v1);
    } else {
        // PV B-frag (k16): b_r = half2(y[k0][g], y[k0+1][g]), k0 = ks*16+r*8+2q
        int u2 = u - 16384;
        int r = u2 & 1, lane = (u2 >> 1) & 31, ks = u2 >> 6;
        int g = lane >> 2, q = lane & 3;
        int k0 = ks * 16 + r * 8 + 2 * q;
        float v0 = (g < 7) ? y[(size_t)k0 * 7 + g]       : 0.f;
        float v1 = (g < 7) ? y[(size_t)(k0 + 1) * 7 + g] : 0.f;
        g_yPf[u2] = packh2(v0, v1);
    }
}

// ---------------------------------------------------------------- fused attention core
// CTA: 256 threads (8 warps x 16 queries = 128 q), keys [split*2048, +2048).
// smem: Sy frags 32K | PV frags 32K
#define ATT_SMEM 65536

__global__ __launch_bounds__(256, 2) void attn_kernel() {
    extern __shared__ char smem[];
    const uint32_t sb = smem_u32(smem);
    const uint32_t SY = sb, PVS = sb + 32768;

    const int t = threadIdx.x, w = t >> 5, lane = t & 31;
    const int g = lane >> 2, q = lane & 3;
    const int qblk = blockIdx.x, split = blockIdx.y;

    // load this split's y-fragments (once)
    {
        const uint32_t* ysrc = g_ySf + split * (256 * 32);
        const uint32_t* psrc = g_yPf + split * (128 * 64);
        #pragma unroll
        for (int i = 0; i < 8; i++) { int f = t + (i << 8); CP16(SY  + f * 16, ysrc + f * 4); }
        #pragma unroll
        for (int i = 0; i < 8; i++) { int f = t + (i << 8); CP16(PVS + f * 16, psrc + f * 4); }
        CP_COMMIT(); CP_WAIT0();
    }
    __syncthreads();

    uint2 qa = g_QKf[(qblk * 8 + w) * 32 + lane];
    uint32_t a8[2] = { qa.x, qa.y };

    float accE[4] = {}, accR[4] = {};
    float zg = 0.f, zg8 = 0.f, rg = 0.f, rg8 = 0.f;

    #pragma unroll 2
    for (int tile = 0; tile < TILES; tile++) {
        // ---- S: 16q x 32keys, K=7(pad8), 4 HMMA ----
        float sc[4][4] = {};
        #pragma unroll
        for (int nt = 0; nt < 4; nt++) {
            uint32_t b;
            lds32(b, SY + (uint32_t)(tile * 512 + nt * 128 + lane * 4));
            mma_f16_k8(sc[nt], a8, b);
        }
        // ---- convert: exp/relu, row sums, pack A-frags ----
        uint32_t eh[4][2], rh[4][2];
        #pragma unroll
        for (int nt = 0; nt < 4; nt++) {
            float e0, e1, e2, e3, r0, r1, r2, r3;
            exp_relu(sc[nt][0], e0, r0);
            exp_relu(sc[nt][1], e1, r1);
            exp_relu(sc[nt][2], e2, r2);
            exp_relu(sc[nt][3], e3, r3);
            eh[nt][0] = packh2(e0, e1); eh[nt][1] = packh2(e2, e3);
            rh[nt][0] = packh2(r0, r1); rh[nt][1] = packh2(r2, r3);
            zg += e0 + e1;  zg8 += e2 + e3;
            rg += r0 + r1;  rg8 += r2 + r3;
        }
        // ---- PV: accEy += E@y, accRy += R@y (N=7 pad8), 4 HMMA ----
        #pragma unroll
        for (int ks = 0; ks < 2; ks++) {
            uint32_t b2[2];
            lds64(b2, PVS + (uint32_t)(tile * 512 + ks * 256 + lane * 8));
            uint32_t aE[4] = { eh[2 * ks][0], eh[2 * ks][1],
                               eh[2 * ks + 1][0], eh[2 * ks + 1][1] };
            uint32_t aR[4] = { rh[2 * ks][0], rh[2 * ks][1],
                               rh[2 * ks + 1][0], rh[2 * ks + 1][1] };
            mma_f16(accE, aE, b2);
            mma_f16(accR, aR, b2);
        }
    }

    // quad-reduce row sums (rows g and g+8)
    zg  += __shfl_xor_sync(0xffffffffu, zg, 1);
    zg  += __shfl_xor_sync(0xffffffffu, zg, 2);
    zg8 += __shfl_xor_sync(0xffffffffu, zg8, 1);
    zg8 += __shfl_xor_sync(0xffffffffu, zg8, 2);
    rg  += __shfl_xor_sync(0xffffffffu, rg, 1);
    rg  += __shfl_xor_sync(0xffffffffu, rg, 2);
    rg8 += __shfl_xor_sync(0xffffffffu, rg8, 1);
    rg8 += __shfl_xor_sync(0xffffffffu, rg8, 2);

    // store partials
    const int qrow = qblk * 128 + w * 16 + g;
    const size_t b8 = (size_t)split * (N_Q * 8);
    *(float2*)&g_pE[b8 + (size_t)qrow * 8 + 2 * q]       = make_float2(accE[0], accE[1]);
    *(float2*)&g_pE[b8 + (size_t)(qrow + 8) * 8 + 2 * q] = make_float2(accE[2], accE[3]);
    *(float2*)&g_pR[b8 + (size_t)qrow * 8 + 2 * q]       = make_float2(accR[0], accR[1]);
    *(float2*)&g_pR[b8 + (size_t)(qrow + 8) * 8 + 2 * q] = make_float2(accR[2], accR[3]);
    if (q == 0) {
        g_pZ[split * N_Q + qrow]     = zg;
        g_pZ[split * N_Q + qrow + 8] = zg8;
        g_pS[split * N_Q + qrow]     = rg;
        g_pS[split * N_Q + qrow + 8] = rg8;
    }
}

// ---------------------------------------------------------------- epilogue: out = c @ Wv
__global__ __launch_bounds__(256) void epi_kernel(const float* __restrict__ Wv,
                                                  float* __restrict__ out) {
    __shared__ float wvs[7 * 256];
    int t = threadIdx.x;
    for (int i = t; i < 7 * 256; i += 256) wvs[i] = Wv[i];
    __syncthreads();
    int w = t >> 5, lane = t & 31;
    int qr = blockIdx.x * 8 + w;
    float z  = g_pZ[qr] + g_pZ[N_Q + qr];
    float rr = g_pS[qr] + g_pS[N_Q + qr];
    float iz = 1.f / z;
    float dn = 1.f / fmaf(0.1f, rr, 1.f);
    float c[7];
    #pragma unroll
    for (int d = 0; d < 7; d++) {
        float e  = g_pE[(size_t)qr * 8 + d] + g_pE[(size_t)N_Q * 8 + (size_t)qr * 8 + d];
        float r2 = g_pR[(size_t)qr * 8 + d] + g_pR[(size_t)N_Q * 8 + (size_t)qr * 8 + d];
        c[d] = fmaf(e, iz, 0.1f * r2) * dn;
    }
    #pragma unroll
    for (int j = 0; j < 8; j++) {
        int n = j * 32 + lane;
        float o = 0.f;
        #pragma unroll
        for (int d = 0; d < 7; d++) o = fmaf(c[d], wvs[d * 256 + n], o);
        out[(size_t)qr * 256 + n] = o;
    }
}

// ---------------------------------------------------------------------------
extern "C" void kernel_launch(void* const* d_in, const int* in_sizes, int n_in,
                              void* d_out, int out_size) {
    const float* x  = (const float*)d_in[0];
    const float* y  = (const float*)d_in[1];
    const float* Wq = (const float*)d_in[2];
    const float* Wk = (const float*)d_in[3];
    const float* Wv = (const float*)d_in[4];
    float* out = (float*)d_out;

    cudaFuncSetAttribute(attn_kernel, cudaFuncAttributeMaxDynamicSharedMemorySize,
                         ATT_SMEM);

    wqk_kernel  <<<1, 256>>>(Wq, Wk);
    ypack_kernel<<<128, 256>>>(y);
    qkp_kernel  <<<128, 256>>>(x);
    attn_kernel <<<dim3(N_Q / 128, KSPLIT), 256, ATT_SMEM>>>();
    epi_kernel  <<<N_Q / 8, 256>>>(Wv, out);
}

// round 10
// speedup vs baseline: 15.1359x; 1.7252x over previous
#include <cuda_runtime.h>
#include <cuda_fp16.h>
#include <cstdint>
#include <math.h>

// AttentionBlock, rank-7 factored form (round 10).
// t = (x·Wqk)·y^T where Wqk = Wq·Wk^T·(log2e/16)  -> MMA outputs log2-domain scores.
// E = 2^t, Rv = relu(t)·ln2.  accEy = E·[y|1], accRy = Rv·[y|1]  (col 7 = Z / Rsum).
// out = ((accEy/Z + 0.1·accRy)/(0.1·Rsum+1)) · Wv.

#define N_Q   16384
#define MCTX  4096
#define S_IN  256
#define D_P   256
#define KSPLIT 4
#define KEYS_PER (MCTX / KSPLIT)   // 1024
#define TILES (KEYS_PER / 32)      // 32
#define GTILES (MCTX / 32)         // 128

// scratch
__device__ float    g_Wqk[S_IN * 8];             // Wq@Wk^T * log2e/16, [256][8] (col7=0)
__device__ uint2    g_QKf [(N_Q / 16) * 32];     // QKp A-frags (k8): [qgroup][lane]
__device__ uint32_t g_ySf [GTILES * 128];        // y^T B-frags (k8,S):  [tile][lane][nt4]
__device__ uint32_t g_yPf [GTILES * 128];        // y B-frags (k16,PV): [tile][lane][ks2][r2]
__device__ float    g_pE  [KSPLIT * N_Q * 8];    // partial accEy (col7 = Z)
__device__ float    g_pR  [KSPLIT * N_Q * 8];    // partial accRy (col7 = Rsum)

#define SCALE_L2E 0.09016844129899994f   /* log2e / 16 */
#define LN2F      0.6931471805599453f

// ---------------------------------------------------------------- helpers
__device__ __forceinline__ uint32_t smem_u32(const void* p) {
    uint32_t a;
    asm("{ .reg .u64 t; cvta.to.shared.u64 t, %1; cvt.u32.u64 %0, t; }" : "=r"(a) : "l"(p));
    return a;
}
__device__ __forceinline__ uint32_t packh2(float lo, float hi) {
    __half2 h = __floats2half2_rn(lo, hi);
    return *(uint32_t*)&h;
}
__device__ __forceinline__ void lds128(uint32_t r[4], uint32_t a) {
    asm volatile("ld.shared.v4.b32 {%0,%1,%2,%3}, [%4];"
        : "=r"(r[0]), "=r"(r[1]), "=r"(r[2]), "=r"(r[3]) : "r"(a));
}
__device__ __forceinline__ void mma_f16_k8(float c[4], const uint32_t a[2], uint32_t b) {
    asm volatile("mma.sync.aligned.m16n8k8.row.col.f32.f16.f16.f32 "
        "{%0,%1,%2,%3}, {%4,%5}, {%6}, {%0,%1,%2,%3};"
        : "+f"(c[0]), "+f"(c[1]), "+f"(c[2]), "+f"(c[3])
        : "r"(a[0]), "r"(a[1]), "r"(b));
}
__device__ __forceinline__ void mma_f16(float c[4], const uint32_t a[4],
                                        uint32_t b0, uint32_t b1) {
    asm volatile("mma.sync.aligned.m16n8k16.row.col.f32.f16.f16.f32 "
        "{%0,%1,%2,%3}, {%4,%5,%6,%7}, {%8,%9}, {%0,%1,%2,%3};"
        : "+f"(c[0]), "+f"(c[1]), "+f"(c[2]), "+f"(c[3])
        : "r"(a[0]), "r"(a[1]), "r"(a[2]), "r"(a[3]), "r"(b0), "r"(b1));
}
#define CP16(dst, src) \
    asm volatile("cp.async.cg.shared.global [%0], [%1], 16;" :: "r"(dst), "l"(src))
#define CP_COMMIT() asm volatile("cp.async.commit_group;" ::: "memory")
#define CP_WAIT0()  asm volatile("cp.async.wait_group 0;" ::: "memory")

// t is already in log2 domain: e = 2^t, rv = relu(t)*ln2. FMA-only, deg-4 poly.
__device__ __forceinline__ void exp2_relu(float t, float& e, float& rv) {
    float k  = t + 12582912.f;
    float nf = k - 12582912.f;
    float f  = t - nf;
    float p  = 0.00961812910762848f;
    p = fmaf(p, f, 0.0555041086648216f);
    p = fmaf(p, f, 0.240226506959101f);
    p = fmaf(p, f, 0.693147180559945f);
    p = fmaf(p, f, 1.0f);
    e  = __uint_as_float(__float_as_uint(p) + (__float_as_uint(k) << 23));
    rv = fmaxf(t, 0.f) * LN2F;
}

// ---------------------------------------------------------------- prep:
// blocks [0,32): Wqk (warp-per-row, coalesced). blocks [32,160): y frag pack.
__global__ __launch_bounds__(256) void prep_kernel(const float* __restrict__ y,
                                                   const float* __restrict__ Wq,
                                                   const float* __restrict__ Wk) {
    int b = blockIdx.x;
    if (b < 32) {
        __shared__ float wks[7 * 256];
        int t = threadIdx.x;
        for (int i = t; i < 7 * 256; i += 256) wks[i] = Wk[i];
        __syncthreads();
        int w = t >> 5, lane = t & 31;
        int row = b * 8 + w;
        float acc[7] = {};
        #pragma unroll
        for (int i = 0; i < 8; i++) {
            int p = i * 32 + lane;
            float v = Wq[row * 256 + p];
            #pragma unroll
            for (int j = 0; j < 7; j++) acc[j] = fmaf(v, wks[j * 256 + p], acc[j]);
        }
        #pragma unroll
        for (int j = 0; j < 7; j++) {
            #pragma unroll
            for (int off = 16; off > 0; off >>= 1)
                acc[j] += __shfl_xor_sync(0xffffffffu, acc[j], off);
        }
        if (lane == 0) {
            #pragma unroll
            for (int j = 0; j < 7; j++) g_Wqk[row * 8 + j] = acc[j] * SCALE_L2E;
            g_Wqk[row * 8 + 7] = 0.f;
        }
    } else {
        int u = (b - 32) * 256 + threadIdx.x;    // [0, 32768)
        if (u < 16384) {
            // S B-frag (k8), layout [tile][lane][nt]: key n = tile*32 + nt*8 + g
            int nt = u & 3, lane = (u >> 2) & 31, tile = u >> 7;
            int g = lane >> 2, q = lane & 3;
            int n = tile * 32 + nt * 8 + g;
            float v0 = (2 * q     < 7) ? y[n * 7 + 2 * q]     : 0.f;
            float v1 = (2 * q + 1 < 7) ? y[n * 7 + 2 * q + 1] : 0.f;   // k-dim pad = 0
            g_ySf[u] = packh2(v0, v1);
        } else {
            // PV B-frag (k16), layout [tile][lane][ks][r]: col 7 = 1.0 (Z/Rsum)
            int u2 = u - 16384;
            int r = u2 & 1, ks = (u2 >> 1) & 1, lane = (u2 >> 2) & 31, tile = u2 >> 7;
            int g = lane >> 2, q = lane & 3;
            int k0 = tile * 32 + ks * 16 + r * 8 + 2 * q;
            float v0 = (g < 7) ? y[(size_t)k0 * 7 + g]       : 1.0f;
            float v1 = (g < 7) ? y[(size_t)(k0 + 1) * 7 + g] : 1.0f;
            g_yPf[u2] = packh2(v0, v1);
        }
    }
}

// ---------------------------------------------------------------- QKp = x@Wqk -> A-frags
__global__ __launch_bounds__(256) void qkp_kernel(const float* __restrict__ x) {
    __shared__ float wqs[2048];
    int t = threadIdx.x;
    for (int i = t; i < 2048; i += 256) wqs[i] = g_Wqk[i];
    __syncthreads();
    int u = blockIdx.x * 256 + t;       // 32768 threads
    int lane = u & 31, qg = u >> 5;
    int g = lane >> 2, q = lane & 3;
    int r0 = qg * 16 + g, r1 = r0 + 8;
    int c0 = 2 * q, c1 = c0 + 1;
    float a00 = 0, a01 = 0, a10 = 0, a11 = 0;
    const float4* x0 = (const float4*)(x + (size_t)r0 * 256);
    const float4* x1 = (const float4*)(x + (size_t)r1 * 256);
    #pragma unroll 4
    for (int k4 = 0; k4 < 64; k4++) {
        float4 v0 = x0[k4], v1 = x1[k4];
        const float* ww = &wqs[k4 * 32];
        a00 = fmaf(v0.x, ww[c0], a00);       a01 = fmaf(v0.x, ww[c1], a01);
        a10 = fmaf(v1.x, ww[c0], a10);       a11 = fmaf(v1.x, ww[c1], a11);
        a00 = fmaf(v0.y, ww[8 + c0], a00);   a01 = fmaf(v0.y, ww[8 + c1], a01);
        a10 = fmaf(v1.y, ww[8 + c0], a10);   a11 = fmaf(v1.y, ww[8 + c1], a11);
        a00 = fmaf(v0.z, ww[16 + c0], a00);  a01 = fmaf(v0.z, ww[16 + c1], a01);
        a10 = fmaf(v1.z, ww[16 + c0], a10);  a11 = fmaf(v1.z, ww[16 + c1], a11);
        a00 = fmaf(v0.w, ww[24 + c0], a00);  a01 = fmaf(v0.w, ww[24 + c1], a01);
        a10 = fmaf(v1.w, ww[24 + c0], a10);  a11 = fmaf(v1.w, ww[24 + c1], a11);
    }
    uint2 o;
    o.x = packh2(a00, a01);
    o.y = packh2(a10, a11);
    g_QKf[u] = o;
}

// ---------------------------------------------------------------- fused attention core
// CTA: 256 threads, 128 queries, keys [split*1024, +1024). smem: 16K + 16K.
#define ATT_SMEM 32768

__global__ __launch_bounds__(256, 4) void attn_kernel() {
    extern __shared__ char smem[];
    const uint32_t sb = smem_u32(smem);
    const uint32_t SY = sb, PVS = sb + 16384;

    const int t = threadIdx.x, w = t >> 5, lane = t & 31;
    const int g = lane >> 2, q = lane & 3;
    const int qblk = blockIdx.x, split = blockIdx.y;

    // load this split's y-fragments (once)
    {
        const uint32_t* ysrc = g_ySf + split * (TILES * 128);
        const uint32_t* psrc = g_yPf + split * (TILES * 128);
        #pragma unroll
        for (int i = 0; i < 4; i++) { int f = t + (i << 8); CP16(SY  + f * 16, ysrc + f * 4); }
        #pragma unroll
        for (int i = 0; i < 4; i++) { int f = t + (i << 8); CP16(PVS + f * 16, psrc + f * 4); }
        CP_COMMIT(); CP_WAIT0();
    }
    __syncthreads();

    uint2 qa = g_QKf[(qblk * 8 + w) * 32 + lane];
    uint32_t a8[2] = { qa.x, qa.y };

    float accE[4] = {}, accR[4] = {};

    #pragma unroll 2
    for (int tile = 0; tile < TILES; tile++) {
        // ---- scores (log2 domain): 16q x 32keys, 4 k8-HMMA, one lds128 ----
        float sc[4][4] = {};
        uint32_t bS[4];
        lds128(bS, SY + (uint32_t)(tile * 128 + lane * 4) * 4);
        mma_f16_k8(sc[0], a8, bS[0]);
        mma_f16_k8(sc[1], a8, bS[1]);
        mma_f16_k8(sc[2], a8, bS[2]);
        mma_f16_k8(sc[3], a8, bS[3]);

        // ---- convert: e = 2^t, rv = relu(t)*ln2; pack A-frags ----
        uint32_t eh[4][2], rh[4][2];
        #pragma unroll
        for (int nt = 0; nt < 4; nt++) {
            float e0, e1, e2, e3, r0, r1, r2, r3;
            exp2_relu(sc[nt][0], e0, r0);
            exp2_relu(sc[nt][1], e1, r1);
            exp2_relu(sc[nt][2], e2, r2);
            exp2_relu(sc[nt][3], e3, r3);
            eh[nt][0] = packh2(e0, e1); eh[nt][1] = packh2(e2, e3);
            rh[nt][0] = packh2(r0, r1); rh[nt][1] = packh2(r2, r3);
        }

        // ---- PV: accEy += E@[y|1], accRy += R@[y|1]; one lds128, 4 k16-HMMA ----
        uint32_t bP[4];
        lds128(bP, PVS + (uint32_t)(tile * 128 + lane * 4) * 4);
        {
            uint32_t aE0[4] = { eh[0][0], eh[0][1], eh[1][0], eh[1][1] };
            uint32_t aR0[4] = { rh[0][0], rh[0][1], rh[1][0], rh[1][1] };
            mma_f16(accE, aE0, bP[0], bP[1]);
            mma_f16(accR, aR0, bP[0], bP[1]);
        }
        {
            uint32_t aE1[4] = { eh[2][0], eh[2][1], eh[3][0], eh[3][1] };
            uint32_t aR1[4] = { rh[2][0], rh[2][1], rh[3][0], rh[3][1] };
            mma_f16(accE, aE1, bP[2], bP[3]);
            mma_f16(accR, aR1, bP[2], bP[3]);
        }
    }

    // store partials (col 7 carries Z / Rsum)
    const int qrow = qblk * 128 + w * 16 + g;
    const size_t b8 = (size_t)split * (N_Q * 8);
    *(float2*)&g_pE[b8 + (size_t)qrow * 8 + 2 * q]       = make_float2(accE[0], accE[1]);
    *(float2*)&g_pE[b8 + (size_t)(qrow + 8) * 8 + 2 * q] = make_float2(accE[2], accE[3]);
    *(float2*)&g_pR[b8 + (size_t)qrow * 8 + 2 * q]       = make_float2(accR[0], accR[1]);
    *(float2*)&g_pR[b8 + (size_t)(qrow + 8) * 8 + 2 * q] = make_float2(accR[2], accR[3]);
}

// ---------------------------------------------------------------- epilogue: out = c @ Wv
__global__ __launch_bounds__(256) void epi_kernel(const float* __restrict__ Wv,
                                                  float* __restrict__ out) {
    __shared__ float wvs[7 * 256];
    int t = threadIdx.x;
    for (int i = t; i < 7 * 256; i += 256) wvs[i] = Wv[i];
    __syncthreads();
    int w = t >> 5, lane = t & 31;
    int qr = blockIdx.x * 8 + w;
    float eacc[8] = {}, racc[8] = {};
    #pragma unroll
    for (int s = 0; s < KSPLIT; s++) {
        const float* pe = &g_pE[(size_t)s * (N_Q * 8) + (size_t)qr * 8];
        const float* pr = &g_pR[(size_t)s * (N_Q * 8) + (size_t)qr * 8];
        float4 e0 = *(const float4*)pe, e1 = *(const float4*)(pe + 4);
        float4 r0 = *(const float4*)pr, r1 = *(const float4*)(pr + 4);
        eacc[0] += e0.x; eacc[1] += e0.y; eacc[2] += e0.z; eacc[3] += e0.w;
        eacc[4] += e1.x; eacc[5] += e1.y; eacc[6] += e1.z; eacc[7] += e1.w;
        racc[0] += r0.x; racc[1] += r0.y; racc[2] += r0.z; racc[3] += r0.w;
        racc[4] += r1.x; racc[5] += r1.y; racc[6] += r1.z; racc[7] += r1.w;
    }
    float iz = 1.f / eacc[7];
    float dn = 1.f / fmaf(0.1f, racc[7], 1.f);
    float c[7];
    #pragma unroll
    for (int d = 0; d < 7; d++)
        c[d] = fmaf(eacc[d], iz, 0.1f * racc[d]) * dn;
    #pragma unroll
    for (int j = 0; j < 8; j++) {
        int n = j * 32 + lane;
        float o = 0.f;
        #pragma unroll
        for (int d = 0; d < 7; d++) o = fmaf(c[d], wvs[d * 256 + n], o);
        out[(size_t)qr * 256 + n] = o;
    }
}

// ---------------------------------------------------------------------------
extern "C" void kernel_launch(void* const* d_in, const int* in_sizes, int n_in,
                              void* d_out, int out_size) {
    const float* x  = (const float*)d_in[0];
    const float* y  = (const float*)d_in[1];
    const float* Wq = (const float*)d_in[2];
    const float* Wk = (const float*)d_in[3];
    const float* Wv = (const float*)d_in[4];
    float* out = (float*)d_out;

    cudaFuncSetAttribute(attn_kernel, cudaFuncAttributeMaxDynamicSharedMemorySize,
                         ATT_SMEM);

    prep_kernel<<<160, 256>>>(y, Wq, Wk);
    qkp_kernel <<<128, 256>>>(x);
    attn_kernel<<<dim3(N_Q / 128, KSPLIT), 256, ATT_SMEM>>>();
    epi_kernel <<<N_Q / 8, 256>>>(Wv, out);
}

// round 11
// speedup vs baseline: 20.6669x; 1.3654x over previous
#include <cuda_runtime.h>
#include <cuda_fp16.h>
#include <cstdint>
#include <math.h>

// AttentionBlock, rank-7 factored form (round 11).
// t = (x·Wqk)·y^T where Wqk = Wq·Wk^T·(log2e/16)  -> MMA outputs log2-domain scores.
// E = 2^t (MUFU ex2), Rv = relu(t) (ln2 folded into epilogue).
// accEy = E·[y|1], accRy = Rv·[y|1]  (col 7 = Z / Rsum').
// out = ((accEy/Z + 0.1·ln2·accRy)/(0.1·ln2·Rsum'+1)) · Wv.

#define N_Q   16384
#define MCTX  4096
#define S_IN  256
#define D_P   256
#define KSPLIT 4
#define KEYS_PER (MCTX / KSPLIT)   // 1024
#define TILES (KEYS_PER / 32)      // 32
#define GTILES (MCTX / 32)         // 128

// scratch
__device__ float    g_Wqk[S_IN * 8];             // Wq@Wk^T * log2e/16, [256][8] (col7=0)
__device__ uint2    g_QKf [(N_Q / 16) * 32];     // QKp A-frags (k8): [qgroup][lane]
__device__ uint32_t g_ySf [GTILES * 128];        // y^T B-frags (k8,S):  [tile][lane][nt4]
__device__ uint32_t g_yPf [GTILES * 128];        // y B-frags (k16,PV): [tile][lane][ks2][r2]
__device__ float    g_pE  [KSPLIT * N_Q * 8];    // partial accEy (col7 = Z)
__device__ float    g_pR  [KSPLIT * N_Q * 8];    // partial accRy (col7 = Rsum')

#define SCALE_L2E 0.09016844129899994f   /* log2e / 16 */
#define C01LN2    0.06931471805599453f   /* 0.1 * ln2 */

// ---------------------------------------------------------------- helpers
__device__ __forceinline__ uint32_t smem_u32(const void* p) {
    uint32_t a;
    asm("{ .reg .u64 t; cvta.to.shared.u64 t, %1; cvt.u32.u64 %0, t; }" : "=r"(a) : "l"(p));
    return a;
}
__device__ __forceinline__ uint32_t packh2(float lo, float hi) {
    __half2 h = __floats2half2_rn(lo, hi);
    return *(uint32_t*)&h;
}
__device__ __forceinline__ float ex2f(float t) {
    float e;
    asm("ex2.approx.f32 %0, %1;" : "=f"(e) : "f"(t));
    return e;
}
__device__ __forceinline__ void lds128(uint32_t r[4], uint32_t a) {
    asm volatile("ld.shared.v4.b32 {%0,%1,%2,%3}, [%4];"
        : "=r"(r[0]), "=r"(r[1]), "=r"(r[2]), "=r"(r[3]) : "r"(a));
}
__device__ __forceinline__ void mma_f16_k8(float c[4], const uint32_t a[2], uint32_t b) {
    asm volatile("mma.sync.aligned.m16n8k8.row.col.f32.f16.f16.f32 "
        "{%0,%1,%2,%3}, {%4,%5}, {%6}, {%0,%1,%2,%3};"
        : "+f"(c[0]), "+f"(c[1]), "+f"(c[2]), "+f"(c[3])
        : "r"(a[0]), "r"(a[1]), "r"(b));
}
__device__ __forceinline__ void mma_f16(float c[4], const uint32_t a[4],
                                        uint32_t b0, uint32_t b1) {
    asm volatile("mma.sync.aligned.m16n8k16.row.col.f32.f16.f16.f32 "
        "{%0,%1,%2,%3}, {%4,%5,%6,%7}, {%8,%9}, {%0,%1,%2,%3};"
        : "+f"(c[0]), "+f"(c[1]), "+f"(c[2]), "+f"(c[3])
        : "r"(a[0]), "r"(a[1]), "r"(a[2]), "r"(a[3]), "r"(b0), "r"(b1));
}
#define CP16(dst, src) \
    asm volatile("cp.async.cg.shared.global [%0], [%1], 16;" :: "r"(dst), "l"(src))
#define CP_COMMIT() asm volatile("cp.async.commit_group;" ::: "memory")
#define CP_WAIT0()  asm volatile("cp.async.wait_group 0;" ::: "memory")

// ---------------------------------------------------------------- prep:
// blocks [0,32): Wqk (warp-per-row, coalesced). blocks [32,160): y frag pack.
__global__ __launch_bounds__(256) void prep_kernel(const float* __restrict__ y,
                                                   const float* __restrict__ Wq,
                                                   const float* __restrict__ Wk) {
    int b = blockIdx.x;
    if (b < 32) {
        __shared__ float wks[7 * 256];
        int t = threadIdx.x;
        for (int i = t; i < 7 * 256; i += 256) wks[i] = Wk[i];
        __syncthreads();
        int w = t >> 5, lane = t & 31;
        int row = b * 8 + w;
        float acc[7] = {};
        #pragma unroll
        for (int i = 0; i < 8; i++) {
            int p = i * 32 + lane;
            float v = Wq[row * 256 + p];
            #pragma unroll
            for (int j = 0; j < 7; j++) acc[j] = fmaf(v, wks[j * 256 + p], acc[j]);
        }
        #pragma unroll
        for (int j = 0; j < 7; j++) {
            #pragma unroll
            for (int off = 16; off > 0; off >>= 1)
                acc[j] += __shfl_xor_sync(0xffffffffu, acc[j], off);
        }
        if (lane == 0) {
            #pragma unroll
            for (int j = 0; j < 7; j++) g_Wqk[row * 8 + j] = acc[j] * SCALE_L2E;
            g_Wqk[row * 8 + 7] = 0.f;
        }
    } else {
        int u = (b - 32) * 256 + threadIdx.x;    // [0, 32768)
        if (u < 16384) {
            // S B-frag (k8), layout [tile][lane][nt]: key n = tile*32 + nt*8 + g
            int nt = u & 3, lane = (u >> 2) & 31, tile = u >> 7;
            int g = lane >> 2, q = lane & 3;
            int n = tile * 32 + nt * 8 + g;
            float v0 = (2 * q     < 7) ? y[n * 7 + 2 * q]     : 0.f;
            float v1 = (2 * q + 1 < 7) ? y[n * 7 + 2 * q + 1] : 0.f;   // k-dim pad = 0
            g_ySf[u] = packh2(v0, v1);
        } else {
            // PV B-frag (k16), layout [tile][lane][ks][r]: col 7 = 1.0 (Z/Rsum)
            int u2 = u - 16384;
            int r = u2 & 1, ks = (u2 >> 1) & 1, lane = (u2 >> 2) & 31, tile = u2 >> 7;
            int g = lane >> 2, q = lane & 3;
            int k0 = tile * 32 + ks * 16 + r * 8 + 2 * q;
            float v0 = (g < 7) ? y[(size_t)k0 * 7 + g]       : 1.0f;
            float v1 = (g < 7) ? y[(size_t)(k0 + 1) * 7 + g] : 1.0f;
            g_yPf[u2] = packh2(v0, v1);
        }
    }
}

// ---------------------------------------------------------------- QKp = x@Wqk -> A-frags
__global__ __launch_bounds__(256) void qkp_kernel(const float* __restrict__ x) {
    __shared__ float wqs[2048];
    int t = threadIdx.x;
    for (int i = t; i < 2048; i += 256) wqs[i] = g_Wqk[i];
    __syncthreads();
    int u = blockIdx.x * 256 + t;       // 32768 threads
    int lane = u & 31, qg = u >> 5;
    int g = lane >> 2, q = lane & 3;
    int r0 = qg * 16 + g, r1 = r0 + 8;
    int c0 = 2 * q, c1 = c0 + 1;
    float a00 = 0, a01 = 0, a10 = 0, a11 = 0;
    const float4* x0 = (const float4*)(x + (size_t)r0 * 256);
    const float4* x1 = (const float4*)(x + (size_t)r1 * 256);
    #pragma unroll 4
    for (int k4 = 0; k4 < 64; k4++) {
        float4 v0 = x0[k4], v1 = x1[k4];
        const float* ww = &wqs[k4 * 32];
        a00 = fmaf(v0.x, ww[c0], a00);       a01 = fmaf(v0.x, ww[c1], a01);
        a10 = fmaf(v1.x, ww[c0], a10);       a11 = fmaf(v1.x, ww[c1], a11);
        a00 = fmaf(v0.y, ww[8 + c0], a00);   a01 = fmaf(v0.y, ww[8 + c1], a01);
        a10 = fmaf(v1.y, ww[8 + c0], a10);   a11 = fmaf(v1.y, ww[8 + c1], a11);
        a00 = fmaf(v0.z, ww[16 + c0], a00);  a01 = fmaf(v0.z, ww[16 + c1], a01);
        a10 = fmaf(v1.z, ww[16 + c0], a10);  a11 = fmaf(v1.z, ww[16 + c1], a11);
        a00 = fmaf(v0.w, ww[24 + c0], a00);  a01 = fmaf(v0.w, ww[24 + c1], a01);
        a10 = fmaf(v1.w, ww[24 + c0], a10);  a11 = fmaf(v1.w, ww[24 + c1], a11);
    }
    uint2 o;
    o.x = packh2(a00, a01);
    o.y = packh2(a10, a11);
    g_QKf[u] = o;
}

// ---------------------------------------------------------------- fused attention core
// CTA: 256 threads, 128 queries, keys [split*1024, +1024). smem: 16K + 16K.
#define ATT_SMEM 32768

__global__ __launch_bounds__(256, 4) void attn_kernel() {
    extern __shared__ char smem[];
    const uint32_t sb = smem_u32(smem);
    const uint32_t SY = sb, PVS = sb + 16384;

    const int t = threadIdx.x, w = t >> 5, lane = t & 31;
    const int g = lane >> 2, q = lane & 3;
    const int qblk = blockIdx.x, split = blockIdx.y;

    // load this split's y-fragments (once)
    {
        const uint32_t* ysrc = g_ySf + split * (TILES * 128);
        const uint32_t* psrc = g_yPf + split * (TILES * 128);
        #pragma unroll
        for (int i = 0; i < 4; i++) { int f = t + (i << 8); CP16(SY  + f * 16, ysrc + f * 4); }
        #pragma unroll
        for (int i = 0; i < 4; i++) { int f = t + (i << 8); CP16(PVS + f * 16, psrc + f * 4); }
        CP_COMMIT(); CP_WAIT0();
    }
    __syncthreads();

    uint2 qa = g_QKf[(qblk * 8 + w) * 32 + lane];
    uint32_t a8[2] = { qa.x, qa.y };

    float accE[4] = {}, accR[4] = {};

    #pragma unroll 2
    for (int tile = 0; tile < TILES; tile++) {
        // ---- scores (log2 domain): 16q x 32keys, 4 k8-HMMA, one lds128 ----
        float sc[4][4] = {};
        uint32_t bS[4];
        lds128(bS, SY + (uint32_t)(tile * 128 + lane * 4) * 4);
        mma_f16_k8(sc[0], a8, bS[0]);
        mma_f16_k8(sc[1], a8, bS[1]);
        mma_f16_k8(sc[2], a8, bS[2]);
        mma_f16_k8(sc[3], a8, bS[3]);

        // ---- convert: e = 2^t via MUFU, rv = relu(t); pack A-frags ----
        uint32_t eh[4][2], rh[4][2];
        #pragma unroll
        for (int nt = 0; nt < 4; nt++) {
            float e0 = ex2f(sc[nt][0]);
            float e1 = ex2f(sc[nt][1]);
            float e2 = ex2f(sc[nt][2]);
            float e3 = ex2f(sc[nt][3]);
            float r0 = fmaxf(sc[nt][0], 0.f);
            float r1 = fmaxf(sc[nt][1], 0.f);
            float r2 = fmaxf(sc[nt][2], 0.f);
            float r3 = fmaxf(sc[nt][3], 0.f);
            eh[nt][0] = packh2(e0, e1); eh[nt][1] = packh2(e2, e3);
            rh[nt][0] = packh2(r0, r1); rh[nt][1] = packh2(r2, r3);
        }

        // ---- PV: accEy += E@[y|1], accRy += R@[y|1]; one lds128, 4 k16-HMMA ----
        uint32_t bP[4];
        lds128(bP, PVS + (uint32_t)(tile * 128 + lane * 4) * 4);
        {
            uint32_t aE0[4] = { eh[0][0], eh[0][1], eh[1][0], eh[1][1] };
            uint32_t aR0[4] = { rh[0][0], rh[0][1], rh[1][0], rh[1][1] };
            mma_f16(accE, aE0, bP[0], bP[1]);
            mma_f16(accR, aR0, bP[0], bP[1]);
        }
        {
            uint32_t aE1[4] = { eh[2][0], eh[2][1], eh[3][0], eh[3][1] };
            uint32_t aR1[4] = { rh[2][0], rh[2][1], rh[3][0], rh[3][1] };
            mma_f16(accE, aE1, bP[2], bP[3]);
            mma_f16(accR, aR1, bP[2], bP[3]);
        }
    }

    // store partials (col 7 carries Z / Rsum')
    const int qrow = qblk * 128 + w * 16 + g;
    const size_t b8 = (size_t)split * (N_Q * 8);
    *(float2*)&g_pE[b8 + (size_t)qrow * 8 + 2 * q]       = make_float2(accE[0], accE[1]);
    *(float2*)&g_pE[b8 + (size_t)(qrow + 8) * 8 + 2 * q] = make_float2(accE[2], accE[3]);
    *(float2*)&g_pR[b8 + (size_t)qrow * 8 + 2 * q]       = make_float2(accR[0], accR[1]);
    *(float2*)&g_pR[b8 + (size_t)(qrow + 8) * 8 + 2 * q] = make_float2(accR[2], accR[3]);
}

// ---------------------------------------------------------------- epilogue: out = c @ Wv
// grid 256 x 256 threads; CTA = 64 query rows. Phase 1: 64 threads reduce
// partials -> c_s[64][8]. Phase 2: Wv float4-columns in regs, coalesced STG.128.
__global__ __launch_bounds__(256) void epi_kernel(const float* __restrict__ Wv,
                                                  float* __restrict__ out) {
    __shared__ float c_s[64][8];
    const int t = threadIdx.x;
    const int rbase = blockIdx.x * 64;

    if (t < 64) {
        int qr = rbase + t;
        float ea[8], ra[8];
        {
            const float* pe = &g_pE[(size_t)qr * 8];
            const float* pr = &g_pR[(size_t)qr * 8];
            float4 e0 = *(const float4*)pe, e1 = *(const float4*)(pe + 4);
            float4 r0 = *(const float4*)pr, r1 = *(const float4*)(pr + 4);
            ea[0] = e0.x; ea[1] = e0.y; ea[2] = e0.z; ea[3] = e0.w;
            ea[4] = e1.x; ea[5] = e1.y; ea[6] = e1.z; ea[7] = e1.w;
            ra[0] = r0.x; ra[1] = r0.y; ra[2] = r0.z; ra[3] = r0.w;
            ra[4] = r1.x; ra[5] = r1.y; ra[6] = r1.z; ra[7] = r1.w;
        }
        #pragma unroll
        for (int s = 1; s < KSPLIT; s++) {
            const float* pe = &g_pE[(size_t)s * (N_Q * 8) + (size_t)qr * 8];
            const float* pr = &g_pR[(size_t)s * (N_Q * 8) + (size_t)qr * 8];
            float4 e0 = *(const float4*)pe, e1 = *(const float4*)(pe + 4);
            float4 r0 = *(const float4*)pr, r1 = *(const float4*)(pr + 4);
            ea[0] += e0.x; ea[1] += e0.y; ea[2] += e0.z; ea[3] += e0.w;
            ea[4] += e1.x; ea[5] += e1.y; ea[6] += e1.z; ea[7] += e1.w;
            ra[0] += r0.x; ra[1] += r0.y; ra[2] += r0.z; ra[3] += r0.w;
            ra[4] += r1.x; ra[5] += r1.y; ra[6] += r1.z; ra[7] += r1.w;
        }
        float iz = 1.f / ea[7];
        float dn = 1.f / fmaf(C01LN2, ra[7], 1.f);
        #pragma unroll
        for (int d = 0; d < 7; d++)
            c_s[t][d] = fmaf(ea[d], iz, C01LN2 * ra[d]) * dn;
        c_s[t][7] = 0.f;
    }
    __syncthreads();

    // phase 2: thread t -> float4-col j = t&63, rows rg*16..+16 with rg = t>>6
    const int j  = t & 63;
    const int rg = t >> 6;
    float4 wv4[7];
    #pragma unroll
    for (int d = 0; d < 7; d++)
        wv4[d] = ((const float4*)(Wv + (size_t)d * 256))[j];

    #pragma unroll 4
    for (int r = 0; r < 16; r++) {
        int row = rg * 16 + r;
        const float* c = c_s[row];
        float4 o;
        o.x = c[0] * wv4[0].x; o.y = c[0] * wv4[0].y;
        o.z = c[0] * wv4[0].z; o.w = c[0] * wv4[0].w;
        #pragma unroll
        for (int d = 1; d < 7; d++) {
            o.x = fmaf(c[d], wv4[d].x, o.x);
            o.y = fmaf(c[d], wv4[d].y, o.y);
            o.z = fmaf(c[d], wv4[d].z, o.z);
            o.w = fmaf(c[d], wv4[d].w, o.w);
        }
        ((float4*)(out + (size_t)(rbase + row) * 256))[j] = o;
    }
}

// ---------------------------------------------------------------------------
extern "C" void kernel_launch(void* const* d_in, const int* in_sizes, int n_in,
                              void* d_out, int out_size) {
    const float* x  = (const float*)d_in[0];
    const float* y  = (const float*)d_in[1];
    const float* Wq = (const float*)d_in[2];
    const float* Wk = (const float*)d_in[3];
    const float* Wv = (const float*)d_in[4];
    float* out = (float*)d_out;

    cudaFuncSetAttribute(attn_kernel, cudaFuncAttributeMaxDynamicSharedMemorySize,
                         ATT_SMEM);

    prep_kernel<<<160, 256>>>(y, Wq, Wk);
    qkp_kernel <<<128, 256>>>(x);
    attn_kernel<<<dim3(N_Q / 128, KSPLIT), 256, ATT_SMEM>>>();
    epi_kernel <<<256, 256>>>(Wv, out);
}

// round 12
// speedup vs baseline: 25.0077x; 1.2100x over previous
#include <cuda_runtime.h>
#include <cuda_fp16.h>
#include <cstdint>
#include <math.h>

// AttentionBlock, rank-7 factored form (round 12).
// t = (x·Wqk)·y^T where Wqk = Wq·Wk^T·(log2e/16)  -> MMA outputs log2-domain scores.
// E = 2^t via ex2.approx.f16x2 (1 MUFU per 2 scores), Rv = relu(t) via max.f16x2.
// accEy = E·[y|1], accRy = Rv·[y|1]  (col 7 = Z / Rsum').
// out = ((accEy/Z + 0.1·ln2·accRy)/(0.1·ln2·Rsum'+1)) · Wv.

#define N_Q   16384
#define MCTX  4096
#define S_IN  256
#define D_P   256
#define KSPLIT 4
#define KEYS_PER (MCTX / KSPLIT)   // 1024
#define TILES (KEYS_PER / 32)      // 32
#define GTILES (MCTX / 32)         // 128

// scratch
__device__ float    g_Wqk[S_IN * 8];             // Wq@Wk^T * log2e/16, [256][8] (col7=0)
__device__ uint2    g_QKf [(N_Q / 16) * 32];     // QKp A-frags (k8): [qgroup][lane]
__device__ uint32_t g_ySf [GTILES * 128];        // y^T B-frags (k8,S):  [tile][lane][nt4]
__device__ uint32_t g_yPf [GTILES * 128];        // y B-frags (k16,PV): [tile][lane][ks2][r2]
__device__ float    g_pE  [KSPLIT * N_Q * 8];    // partial accEy (col7 = Z)
__device__ float    g_pR  [KSPLIT * N_Q * 8];    // partial accRy (col7 = Rsum')

#define SCALE_L2E 0.09016844129899994f   /* log2e / 16 */
#define C01LN2    0.06931471805599453f   /* 0.1 * ln2 */

// ---------------------------------------------------------------- helpers
__device__ __forceinline__ uint32_t smem_u32(const void* p) {
    uint32_t a;
    asm("{ .reg .u64 t; cvta.to.shared.u64 t, %1; cvt.u32.u64 %0, t; }" : "=r"(a) : "l"(p));
    return a;
}
__device__ __forceinline__ uint32_t packh2(float lo, float hi) {
    __half2 h = __floats2half2_rn(lo, hi);
    return *(uint32_t*)&h;
}
__device__ __forceinline__ uint32_t h2ex2(uint32_t t) {
    uint32_t e;
    asm("ex2.approx.f16x2 %0, %1;" : "=r"(e) : "r"(t));
    return e;
}
__device__ __forceinline__ uint32_t h2relu(uint32_t t) {
    uint32_t r;
    asm("max.f16x2 %0, %1, %2;" : "=r"(r) : "r"(t), "r"(0u));
    return r;
}
__device__ __forceinline__ void lds128(uint32_t r[4], uint32_t a) {
    asm volatile("ld.shared.v4.b32 {%0,%1,%2,%3}, [%4];"
        : "=r"(r[0]), "=r"(r[1]), "=r"(r[2]), "=r"(r[3]) : "r"(a));
}
__device__ __forceinline__ void mma_f16_k8(float c[4], const uint32_t a[2], uint32_t b) {
    asm volatile("mma.sync.aligned.m16n8k8.row.col.f32.f16.f16.f32 "
        "{%0,%1,%2,%3}, {%4,%5}, {%6}, {%0,%1,%2,%3};"
        : "+f"(c[0]), "+f"(c[1]), "+f"(c[2]), "+f"(c[3])
        : "r"(a[0]), "r"(a[1]), "r"(b));
}
__device__ __forceinline__ void mma_f16(float c[4], const uint32_t a[4],
                                        uint32_t b0, uint32_t b1) {
    asm volatile("mma.sync.aligned.m16n8k16.row.col.f32.f16.f16.f32 "
        "{%0,%1,%2,%3}, {%4,%5,%6,%7}, {%8,%9}, {%0,%1,%2,%3};"
        : "+f"(c[0]), "+f"(c[1]), "+f"(c[2]), "+f"(c[3])
        : "r"(a[0]), "r"(a[1]), "r"(a[2]), "r"(a[3]), "r"(b0), "r"(b1));
}
#define CP16(dst, src) \
    asm volatile("cp.async.cg.shared.global [%0], [%1], 16;" :: "r"(dst), "l"(src))
#define CP_COMMIT() asm volatile("cp.async.commit_group;" ::: "memory")
#define CP_WAIT0()  asm volatile("cp.async.wait_group 0;" ::: "memory")

// ---------------------------------------------------------------- prep:
// blocks [0,32): Wqk (warp-per-row, coalesced). blocks [32,160): y frag pack.
__global__ __launch_bounds__(256) void prep_kernel(const float* __restrict__ y,
                                                   const float* __restrict__ Wq,
                                                   const float* __restrict__ Wk) {
    int b = blockIdx.x;
    if (b < 32) {
        __shared__ float wks[7 * 256];
        int t = threadIdx.x;
        for (int i = t; i < 7 * 256; i += 256) wks[i] = Wk[i];
        __syncthreads();
        int w = t >> 5, lane = t & 31;
        int row = b * 8 + w;
        float acc[7] = {};
        #pragma unroll
        for (int i = 0; i < 8; i++) {
            int p = i * 32 + lane;
            float v = Wq[row * 256 + p];
            #pragma unroll
            for (int j = 0; j < 7; j++) acc[j] = fmaf(v, wks[j * 256 + p], acc[j]);
        }
        #pragma unroll
        for (int j = 0; j < 7; j++) {
            #pragma unroll
            for (int off = 16; off > 0; off >>= 1)
                acc[j] += __shfl_xor_sync(0xffffffffu, acc[j], off);
        }
        if (lane == 0) {
            #pragma unroll
            for (int j = 0; j < 7; j++) g_Wqk[row * 8 + j] = acc[j] * SCALE_L2E;
            g_Wqk[row * 8 + 7] = 0.f;
        }
    } else {
        int u = (b - 32) * 256 + threadIdx.x;    // [0, 32768)
        if (u < 16384) {
            // S B-frag (k8), layout [tile][lane][nt]: key n = tile*32 + nt*8 + g
            int nt = u & 3, lane = (u >> 2) & 31, tile = u >> 7;
            int g = lane >> 2, q = lane & 3;
            int n = tile * 32 + nt * 8 + g;
            float v0 = (2 * q     < 7) ? y[n * 7 + 2 * q]     : 0.f;
            float v1 = (2 * q + 1 < 7) ? y[n * 7 + 2 * q + 1] : 0.f;   // k-dim pad = 0
            g_ySf[u] = packh2(v0, v1);
        } else {
            // PV B-frag (k16), layout [tile][lane][ks][r]: col 7 = 1.0 (Z/Rsum)
            int u2 = u - 16384;
            int r = u2 & 1, ks = (u2 >> 1) & 1, lane = (u2 >> 2) & 31, tile = u2 >> 7;
            int g = lane >> 2, q = lane & 3;
            int k0 = tile * 32 + ks * 16 + r * 8 + 2 * q;
            float v0 = (g < 7) ? y[(size_t)k0 * 7 + g]       : 1.0f;
            float v1 = (g < 7) ? y[(size_t)(k0 + 1) * 7 + g] : 1.0f;
            g_yPf[u2] = packh2(v0, v1);
        }
    }
}

// ---------------------------------------------------------------- QKp = x@Wqk -> A-frags
__global__ __launch_bounds__(256) void qkp_kernel(const float* __restrict__ x) {
    __shared__ float wqs[2048];
    int t = threadIdx.x;
    for (int i = t; i < 2048; i += 256) wqs[i] = g_Wqk[i];
    __syncthreads();
    int u = blockIdx.x * 256 + t;       // 32768 threads
    int lane = u & 31, qg = u >> 5;
    int g = lane >> 2, q = lane & 3;
    int r0 = qg * 16 + g, r1 = r0 + 8;
    int c0 = 2 * q, c1 = c0 + 1;
    float a00 = 0, a01 = 0, a10 = 0, a11 = 0;
    const float4* x0 = (const float4*)(x + (size_t)r0 * 256);
    const float4* x1 = (const float4*)(x + (size_t)r1 * 256);
    #pragma unroll 4
    for (int k4 = 0; k4 < 64; k4++) {
        float4 v0 = x0[k4], v1 = x1[k4];
        const float* ww = &wqs[k4 * 32];
        a00 = fmaf(v0.x, ww[c0], a00);       a01 = fmaf(v0.x, ww[c1], a01);
        a10 = fmaf(v1.x, ww[c0], a10);       a11 = fmaf(v1.x, ww[c1], a11);
        a00 = fmaf(v0.y, ww[8 + c0], a00);   a01 = fmaf(v0.y, ww[8 + c1], a01);
        a10 = fmaf(v1.y, ww[8 + c0], a10);   a11 = fmaf(v1.y, ww[8 + c1], a11);
        a00 = fmaf(v0.z, ww[16 + c0], a00);  a01 = fmaf(v0.z, ww[16 + c1], a01);
        a10 = fmaf(v1.z, ww[16 + c0], a10);  a11 = fmaf(v1.z, ww[16 + c1], a11);
        a00 = fmaf(v0.w, ww[24 + c0], a00);  a01 = fmaf(v0.w, ww[24 + c1], a01);
        a10 = fmaf(v1.w, ww[24 + c0], a10);  a11 = fmaf(v1.w, ww[24 + c1], a11);
    }
    uint2 o;
    o.x = packh2(a00, a01);
    o.y = packh2(a10, a11);
    g_QKf[u] = o;
}

// ---------------------------------------------------------------- fused attention core
// CTA: 256 threads, 128 queries, keys [split*1024, +1024). smem: 16K + 16K.
#define ATT_SMEM 32768

__global__ __launch_bounds__(256, 4) void attn_kernel() {
    extern __shared__ char smem[];
    const uint32_t sb = smem_u32(smem);
    const uint32_t SY = sb, PVS = sb + 16384;

    const int t = threadIdx.x, w = t >> 5, lane = t & 31;
    const int g = lane >> 2, q = lane & 3;
    const int qblk = blockIdx.x, split = blockIdx.y;

    // load this split's y-fragments (once)
    {
        const uint32_t* ysrc = g_ySf + split * (TILES * 128);
        const uint32_t* psrc = g_yPf + split * (TILES * 128);
        #pragma unroll
        for (int i = 0; i < 4; i++) { int f = t + (i << 8); CP16(SY  + f * 16, ysrc + f * 4); }
        #pragma unroll
        for (int i = 0; i < 4; i++) { int f = t + (i << 8); CP16(PVS + f * 16, psrc + f * 4); }
        CP_COMMIT(); CP_WAIT0();
    }
    __syncthreads();

    uint2 qa = g_QKf[(qblk * 8 + w) * 32 + lane];
    uint32_t a8[2] = { qa.x, qa.y };

    float accE[4] = {}, accR[4] = {};

    #pragma unroll 2
    for (int tile = 0; tile < TILES; tile++) {
        // ---- scores (log2 domain): 16q x 32keys, 4 k8-HMMA, one lds128 ----
        float sc[4][4] = {};
        uint32_t bS[4];
        lds128(bS, SY + (uint32_t)(tile * 128 + lane * 4) * 4);
        mma_f16_k8(sc[0], a8, bS[0]);
        mma_f16_k8(sc[1], a8, bS[1]);
        mma_f16_k8(sc[2], a8, bS[2]);
        mma_f16_k8(sc[3], a8, bS[3]);

        // ---- convert in half2: pack t, E = ex2.f16x2, Rv = max.f16x2 ----
        uint32_t eh[4][2], rh[4][2];
        #pragma unroll
        for (int nt = 0; nt < 4; nt++) {
            uint32_t t01 = packh2(sc[nt][0], sc[nt][1]);
            uint32_t t23 = packh2(sc[nt][2], sc[nt][3]);
            eh[nt][0] = h2ex2(t01);   eh[nt][1] = h2ex2(t23);
            rh[nt][0] = h2relu(t01);  rh[nt][1] = h2relu(t23);
        }

        // ---- PV: accEy += E@[y|1], accRy += R@[y|1]; one lds128, 4 k16-HMMA ----
        uint32_t bP[4];
        lds128(bP, PVS + (uint32_t)(tile * 128 + lane * 4) * 4);
        {
            uint32_t aE0[4] = { eh[0][0], eh[0][1], eh[1][0], eh[1][1] };
            uint32_t aR0[4] = { rh[0][0], rh[0][1], rh[1][0], rh[1][1] };
            mma_f16(accE, aE0, bP[0], bP[1]);
            mma_f16(accR, aR0, bP[0], bP[1]);
        }
        {
            uint32_t aE1[4] = { eh[2][0], eh[2][1], eh[3][0], eh[3][1] };
            uint32_t aR1[4] = { rh[2][0], rh[2][1], rh[3][0], rh[3][1] };
            mma_f16(accE, aE1, bP[2], bP[3]);
            mma_f16(accR, aR1, bP[2], bP[3]);
        }
    }

    // store partials (col 7 carries Z / Rsum')
    const int qrow = qblk * 128 + w * 16 + g;
    const size_t b8 = (size_t)split * (N_Q * 8);
    *(float2*)&g_pE[b8 + (size_t)qrow * 8 + 2 * q]       = make_float2(accE[0], accE[1]);
    *(float2*)&g_pE[b8 + (size_t)(qrow + 8) * 8 + 2 * q] = make_float2(accE[2], accE[3]);
    *(float2*)&g_pR[b8 + (size_t)qrow * 8 + 2 * q]       = make_float2(accR[0], accR[1]);
    *(float2*)&g_pR[b8 + (size_t)(qrow + 8) * 8 + 2 * q] = make_float2(accR[2], accR[3]);
}

// ---------------------------------------------------------------- epilogue: out = c @ Wv
// grid 1024 x 256 threads; CTA = 16 query rows (high occupancy: ~7 CTAs/SM).
// Phase 1: 16 threads reduce partials -> c_s[16][8]. Phase 2: Wv float4-columns
// in regs, each thread writes 4 rows, coalesced STG.128.
__global__ __launch_bounds__(256) void epi_kernel(const float* __restrict__ Wv,
                                                  float* __restrict__ out) {
    __shared__ float c_s[16][8];
    const int t = threadIdx.x;
    const int rbase = blockIdx.x * 16;

    if (t < 16) {
        int qr = rbase + t;
        float ea[8], ra[8];
        {
            const float* pe = &g_pE[(size_t)qr * 8];
            const float* pr = &g_pR[(size_t)qr * 8];
            float4 e0 = *(const float4*)pe, e1 = *(const float4*)(pe + 4);
            float4 r0 = *(const float4*)pr, r1 = *(const float4*)(pr + 4);
            ea[0] = e0.x; ea[1] = e0.y; ea[2] = e0.z; ea[3] = e0.w;
            ea[4] = e1.x; ea[5] = e1.y; ea[6] = e1.z; ea[7] = e1.w;
            ra[0] = r0.x; ra[1] = r0.y; ra[2] = r0.z; ra[3] = r0.w;
            ra[4] = r1.x; ra[5] = r1.y; ra[6] = r1.z; ra[7] = r1.w;
        }
        #pragma unroll
        for (int s = 1; s < KSPLIT; s++) {
            const float* pe = &g_pE[(size_t)s * (N_Q * 8) + (size_t)qr * 8];
            const float* pr = &g_pR[(size_t)s * (N_Q * 8) + (size_t)qr * 8];
            float4 e0 = *(const float4*)pe, e1 = *(const float4*)(pe + 4);
            float4 r0 = *(const float4*)pr, r1 = *(const float4*)(pr + 4);
            ea[0] += e0.x; ea[1] += e0.y; ea[2] += e0.z; ea[3] += e0.w;
            ea[4] += e1.x; ea[5] += e1.y; ea[6] += e1.z; ea[7] += e1.w;
            ra[0] += r0.x; ra[1] += r0.y; ra[2] += r0.z; ra[3] += r0.w;
            ra[4] += r1.x; ra[5] += r1.y; ra[6] += r1.z; ra[7] += r1.w;
        }
        float iz = 1.f / ea[7];
        float dn = 1.f / fmaf(C01LN2, ra[7], 1.f);
        #pragma unroll
        for (int d = 0; d < 7; d++)
            c_s[t][d] = fmaf(ea[d], iz, C01LN2 * ra[d]) * dn;
        c_s[t][7] = 0.f;
    }
    __syncthreads();

    // phase 2: thread t -> float4-col j = t&63, rows rg*4..+4 with rg = t>>6
    const int j  = t & 63;
    const int rg = t >> 6;
    float4 wv4[7];
    #pragma unroll
    for (int d = 0; d < 7; d++)
        wv4[d] = ((const float4*)(Wv + (size_t)d * 256))[j];

    #pragma unroll
    for (int r = 0; r < 4; r++) {
        int row = rg * 4 + r;
        const float* c = c_s[row];
        float4 o;
        o.x = c[0] * wv4[0].x; o.y = c[0] * wv4[0].y;
        o.z = c[0] * wv4[0].z; o.w = c[0] * wv4[0].w;
        #pragma unroll
        for (int d = 1; d < 7; d++) {
            o.x = fmaf(c[d], wv4[d].x, o.x);
            o.y = fmaf(c[d], wv4[d].y, o.y);
            o.z = fmaf(c[d], wv4[d].z, o.z);
            o.w = fmaf(c[d], wv4[d].w, o.w);
        }
        ((float4*)(out + (size_t)(rbase + row) * 256))[j] = o;
    }
}

// ---------------------------------------------------------------------------
extern "C" void kernel_launch(void* const* d_in, const int* in_sizes, int n_in,
                              void* d_out, int out_size) {
    const float* x  = (const float*)d_in[0];
    const float* y  = (const float*)d_in[1];
    const float* Wq = (const float*)d_in[2];
    const float* Wk = (const float*)d_in[3];
    const float* Wv = (const float*)d_in[4];
    float* out = (float*)d_out;

    cudaFuncSetAttribute(attn_kernel, cudaFuncAttributeMaxDynamicSharedMemorySize,
                         ATT_SMEM);

    prep_kernel<<<160, 256>>>(y, Wq, Wk);
    qkp_kernel <<<128, 256>>>(x);
    attn_kernel<<<dim3(N_Q / 128, KSPLIT), 256, ATT_SMEM>>>();
    epi_kernel <<<1024, 256>>>(Wv, out);
}

// round 13
// speedup vs baseline: 26.6386x; 1.0652x over previous
#include <cuda_runtime.h>
#include <cuda_fp16.h>
#include <cstdint>
#include <math.h>

// AttentionBlock, rank-7 factored form (round 13).
// t = (x·Wqk)·y^T where Wqk = Wq·Wk^T·(log2e/16)  -> MMA outputs log2-domain scores.
// E = 2^t via ex2.approx.f16x2, Rv = relu(t) via max.f16x2.
// accEy = E·[y|1], accRy = Rv·[y|1]  (col 7 = Z / Rsum').
// out = ((accEy/Z + 0.1·ln2·accRy)/(0.1·ln2·Rsum'+1)) · Wv.
// Round 13: KSPLIT 8 (SM load balance 7:6 instead of 4:3), epi phase-1
// parallelized across all 256 threads (quad shuffle reduce).

#define N_Q   16384
#define MCTX  4096
#define S_IN  256
#define D_P   256
#define KSPLIT 8
#define KEYS_PER (MCTX / KSPLIT)   // 512
#define TILES (KEYS_PER / 32)      // 16
#define GTILES (MCTX / 32)         // 128

// scratch
__device__ float    g_Wqk[S_IN * 8];             // Wq@Wk^T * log2e/16, [256][8] (col7=0)
__device__ uint2    g_QKf [(N_Q / 16) * 32];     // QKp A-frags (k8): [qgroup][lane]
__device__ uint32_t g_ySf [GTILES * 128];        // y^T B-frags (k8,S):  [tile][lane][nt4]
__device__ uint32_t g_yPf [GTILES * 128];        // y B-frags (k16,PV): [tile][lane][ks2][r2]
__device__ float    g_pE  [KSPLIT * N_Q * 8];    // partial accEy (col7 = Z)
__device__ float    g_pR  [KSPLIT * N_Q * 8];    // partial accRy (col7 = Rsum')

#define SCALE_L2E 0.09016844129899994f   /* log2e / 16 */
#define C01LN2    0.06931471805599453f   /* 0.1 * ln2 */

// ---------------------------------------------------------------- helpers
__device__ __forceinline__ uint32_t smem_u32(const void* p) {
    uint32_t a;
    asm("{ .reg .u64 t; cvta.to.shared.u64 t, %1; cvt.u32.u64 %0, t; }" : "=r"(a) : "l"(p));
    return a;
}
__device__ __forceinline__ uint32_t packh2(float lo, float hi) {
    __half2 h = __floats2half2_rn(lo, hi);
    return *(uint32_t*)&h;
}
__device__ __forceinline__ uint32_t h2ex2(uint32_t t) {
    uint32_t e;
    asm("ex2.approx.f16x2 %0, %1;" : "=r"(e) : "r"(t));
    return e;
}
__device__ __forceinline__ uint32_t h2relu(uint32_t t) {
    uint32_t r;
    asm("max.f16x2 %0, %1, %2;" : "=r"(r) : "r"(t), "r"(0u));
    return r;
}
__device__ __forceinline__ void lds128(uint32_t r[4], uint32_t a) {
    asm volatile("ld.shared.v4.b32 {%0,%1,%2,%3}, [%4];"
        : "=r"(r[0]), "=r"(r[1]), "=r"(r[2]), "=r"(r[3]) : "r"(a));
}
__device__ __forceinline__ void mma_f16_k8(float c[4], const uint32_t a[2], uint32_t b) {
    asm volatile("mma.sync.aligned.m16n8k8.row.col.f32.f16.f16.f32 "
        "{%0,%1,%2,%3}, {%4,%5}, {%6}, {%0,%1,%2,%3};"
        : "+f"(c[0]), "+f"(c[1]), "+f"(c[2]), "+f"(c[3])
        : "r"(a[0]), "r"(a[1]), "r"(b));
}
__device__ __forceinline__ void mma_f16(float c[4], const uint32_t a[4],
                                        uint32_t b0, uint32_t b1) {
    asm volatile("mma.sync.aligned.m16n8k16.row.col.f32.f16.f16.f32 "
        "{%0,%1,%2,%3}, {%4,%5,%6,%7}, {%8,%9}, {%0,%1,%2,%3};"
        : "+f"(c[0]), "+f"(c[1]), "+f"(c[2]), "+f"(c[3])
        : "r"(a[0]), "r"(a[1]), "r"(a[2]), "r"(a[3]), "r"(b0), "r"(b1));
}
#define CP16(dst, src) \
    asm volatile("cp.async.cg.shared.global [%0], [%1], 16;" :: "r"(dst), "l"(src))
#define CP_COMMIT() asm volatile("cp.async.commit_group;" ::: "memory")
#define CP_WAIT0()  asm volatile("cp.async.wait_group 0;" ::: "memory")

// ---------------------------------------------------------------- prep:
// blocks [0,32): Wqk (warp-per-row, coalesced). blocks [32,160): y frag pack.
__global__ __launch_bounds__(256) void prep_kernel(const float* __restrict__ y,
                                                   const float* __restrict__ Wq,
                                                   const float* __restrict__ Wk) {
    int b = blockIdx.x;
    if (b < 32) {
        __shared__ float wks[7 * 256];
        int t = threadIdx.x;
        for (int i = t; i < 7 * 256; i += 256) wks[i] = Wk[i];
        __syncthreads();
        int w = t >> 5, lane = t & 31;
        int row = b * 8 + w;
        float acc[7] = {};
        #pragma unroll
        for (int i = 0; i < 8; i++) {
            int p = i * 32 + lane;
            float v = Wq[row * 256 + p];
            #pragma unroll
            for (int j = 0; j < 7; j++) acc[j] = fmaf(v, wks[j * 256 + p], acc[j]);
        }
        #pragma unroll
        for (int j = 0; j < 7; j++) {
            #pragma unroll
            for (int off = 16; off > 0; off >>= 1)
                acc[j] += __shfl_xor_sync(0xffffffffu, acc[j], off);
        }
        if (lane == 0) {
            #pragma unroll
            for (int j = 0; j < 7; j++) g_Wqk[row * 8 + j] = acc[j] * SCALE_L2E;
            g_Wqk[row * 8 + 7] = 0.f;
        }
    } else {
        int u = (b - 32) * 256 + threadIdx.x;    // [0, 32768)
        if (u < 16384) {
            // S B-frag (k8), layout [tile][lane][nt]: key n = tile*32 + nt*8 + g
            int nt = u & 3, lane = (u >> 2) & 31, tile = u >> 7;
            int g = lane >> 2, q = lane & 3;
            int n = tile * 32 + nt * 8 + g;
            float v0 = (2 * q     < 7) ? y[n * 7 + 2 * q]     : 0.f;
            float v1 = (2 * q + 1 < 7) ? y[n * 7 + 2 * q + 1] : 0.f;   // k-dim pad = 0
            g_ySf[u] = packh2(v0, v1);
        } else {
            // PV B-frag (k16), layout [tile][lane][ks][r]: col 7 = 1.0 (Z/Rsum)
            int u2 = u - 16384;
            int r = u2 & 1, ks = (u2 >> 1) & 1, lane = (u2 >> 2) & 31, tile = u2 >> 7;
            int g = lane >> 2, q = lane & 3;
            int k0 = tile * 32 + ks * 16 + r * 8 + 2 * q;
            float v0 = (g < 7) ? y[(size_t)k0 * 7 + g]       : 1.0f;
            float v1 = (g < 7) ? y[(size_t)(k0 + 1) * 7 + g] : 1.0f;
            g_yPf[u2] = packh2(v0, v1);
        }
    }
}

// ---------------------------------------------------------------- QKp = x@Wqk -> A-frags
__global__ __launch_bounds__(256) void qkp_kernel(const float* __restrict__ x) {
    __shared__ float wqs[2048];
    int t = threadIdx.x;
    for (int i = t; i < 2048; i += 256) wqs[i] = g_Wqk[i];
    __syncthreads();
    int u = blockIdx.x * 256 + t;       // 32768 threads
    int lane = u & 31, qg = u >> 5;
    int g = lane >> 2, q = lane & 3;
    int r0 = qg * 16 + g, r1 = r0 + 8;
    int c0 = 2 * q, c1 = c0 + 1;
    float a00 = 0, a01 = 0, a10 = 0, a11 = 0;
    const float4* x0 = (const float4*)(x + (size_t)r0 * 256);
    const float4* x1 = (const float4*)(x + (size_t)r1 * 256);
    #pragma unroll 4
    for (int k4 = 0; k4 < 64; k4++) {
        float4 v0 = x0[k4], v1 = x1[k4];
        const float* ww = &wqs[k4 * 32];
        a00 = fmaf(v0.x, ww[c0], a00);       a01 = fmaf(v0.x, ww[c1], a01);
        a10 = fmaf(v1.x, ww[c0], a10);       a11 = fmaf(v1.x, ww[c1], a11);
        a00 = fmaf(v0.y, ww[8 + c0], a00);   a01 = fmaf(v0.y, ww[8 + c1], a01);
        a10 = fmaf(v1.y, ww[8 + c0], a10);   a11 = fmaf(v1.y, ww[8 + c1], a11);
        a00 = fmaf(v0.z, ww[16 + c0], a00);  a01 = fmaf(v0.z, ww[16 + c1], a01);
        a10 = fmaf(v1.z, ww[16 + c0], a10);  a11 = fmaf(v1.z, ww[16 + c1], a11);
        a00 = fmaf(v0.w, ww[24 + c0], a00);  a01 = fmaf(v0.w, ww[24 + c1], a01);
        a10 = fmaf(v1.w, ww[24 + c0], a10);  a11 = fmaf(v1.w, ww[24 + c1], a11);
    }
    uint2 o;
    o.x = packh2(a00, a01);
    o.y = packh2(a10, a11);
    g_QKf[u] = o;
}

// ---------------------------------------------------------------- fused attention core
// CTA: 256 threads, 128 queries, keys [split*512, +512). smem: 8K + 8K.
#define ATT_SMEM 16384

__global__ __launch_bounds__(256, 4) void attn_kernel() {
    extern __shared__ char smem[];
    const uint32_t sb = smem_u32(smem);
    const uint32_t SY = sb, PVS = sb + 8192;

    const int t = threadIdx.x, w = t >> 5, lane = t & 31;
    const int g = lane >> 2, q = lane & 3;
    const int qblk = blockIdx.x, split = blockIdx.y;

    // load this split's y-fragments (once)
    {
        const uint32_t* ysrc = g_ySf + split * (TILES * 128);
        const uint32_t* psrc = g_yPf + split * (TILES * 128);
        #pragma unroll
        for (int i = 0; i < 2; i++) { int f = t + (i << 8); CP16(SY  + f * 16, ysrc + f * 4); }
        #pragma unroll
        for (int i = 0; i < 2; i++) { int f = t + (i << 8); CP16(PVS + f * 16, psrc + f * 4); }
        CP_COMMIT(); CP_WAIT0();
    }
    __syncthreads();

    uint2 qa = g_QKf[(qblk * 8 + w) * 32 + lane];
    uint32_t a8[2] = { qa.x, qa.y };

    float accE[4] = {}, accR[4] = {};

    #pragma unroll 2
    for (int tile = 0; tile < TILES; tile++) {
        // ---- scores (log2 domain): 16q x 32keys, 4 k8-HMMA, one lds128 ----
        float sc[4][4] = {};
        uint32_t bS[4];
        lds128(bS, SY + (uint32_t)(tile * 128 + lane * 4) * 4);
        mma_f16_k8(sc[0], a8, bS[0]);
        mma_f16_k8(sc[1], a8, bS[1]);
        mma_f16_k8(sc[2], a8, bS[2]);
        mma_f16_k8(sc[3], a8, bS[3]);

        // ---- convert in half2: pack t, E = ex2.f16x2, Rv = max.f16x2 ----
        uint32_t eh[4][2], rh[4][2];
        #pragma unroll
        for (int nt = 0; nt < 4; nt++) {
            uint32_t t01 = packh2(sc[nt][0], sc[nt][1]);
            uint32_t t23 = packh2(sc[nt][2], sc[nt][3]);
            eh[nt][0] = h2ex2(t01);   eh[nt][1] = h2ex2(t23);
            rh[nt][0] = h2relu(t01);  rh[nt][1] = h2relu(t23);
        }

        // ---- PV: accEy += E@[y|1], accRy += R@[y|1]; one lds128, 4 k16-HMMA ----
        uint32_t bP[4];
        lds128(bP, PVS + (uint32_t)(tile * 128 + lane * 4) * 4);
        {
            uint32_t aE0[4] = { eh[0][0], eh[0][1], eh[1][0], eh[1][1] };
            uint32_t aR0[4] = { rh[0][0], rh[0][1], rh[1][0], rh[1][1] };
            mma_f16(accE, aE0, bP[0], bP[1]);
            mma_f16(accR, aR0, bP[0], bP[1]);
        }
        {
            uint32_t aE1[4] = { eh[2][0], eh[2][1], eh[3][0], eh[3][1] };
            uint32_t aR1[4] = { rh[2][0], rh[2][1], rh[3][0], rh[3][1] };
            mma_f16(accE, aE1, bP[2], bP[3]);
            mma_f16(accR, aR1, bP[2], bP[3]);
        }
    }

    // store partials (col 7 carries Z / Rsum')
    const int qrow = qblk * 128 + w * 16 + g;
    const size_t b8 = (size_t)split * (N_Q * 8);
    *(float2*)&g_pE[b8 + (size_t)qrow * 8 + 2 * q]       = make_float2(accE[0], accE[1]);
    *(float2*)&g_pE[b8 + (size_t)(qrow + 8) * 8 + 2 * q] = make_float2(accE[2], accE[3]);
    *(float2*)&g_pR[b8 + (size_t)qrow * 8 + 2 * q]       = make_float2(accR[0], accR[1]);
    *(float2*)&g_pR[b8 + (size_t)(qrow + 8) * 8 + 2 * q] = make_float2(accR[2], accR[3]);
}

// ---------------------------------------------------------------- epilogue: out = c @ Wv
// grid 256 x 256 threads; CTA = 64 query rows.
// Phase 1 (ALL 256 threads): thread (row = t>>2, sp = t&3) loads 2 splits'
// partials (8 independent LDG.128), quad shuffle-xor reduce, sp==0 writes c_s.
// Phase 2: Wv float4-columns in regs, 16 rows/thread, coalesced STG.128.
__global__ __launch_bounds__(256) void epi_kernel(const float* __restrict__ Wv,
                                                  float* __restrict__ out) {
    __shared__ float c_s[64][8];
    const int t = threadIdx.x;
    const int rbase = blockIdx.x * 64;

    // ---- phase 1 ----
    {
        const int row = t >> 2, sp = t & 3;
        const int qr = rbase + row;
        float ea[8] = {}, ra[8] = {};
        #pragma unroll
        for (int i = 0; i < 2; i++) {
            int s = sp * 2 + i;
            const float* pe = &g_pE[(size_t)s * (N_Q * 8) + (size_t)qr * 8];
            const float* pr = &g_pR[(size_t)s * (N_Q * 8) + (size_t)qr * 8];
            float4 e0 = *(const float4*)pe, e1 = *(const float4*)(pe + 4);
            float4 r0 = *(const float4*)pr, r1 = *(const float4*)(pr + 4);
            ea[0] += e0.x; ea[1] += e0.y; ea[2] += e0.z; ea[3] += e0.w;
            ea[4] += e1.x; ea[5] += e1.y; ea[6] += e1.z; ea[7] += e1.w;
            ra[0] += r0.x; ra[1] += r0.y; ra[2] += r0.z; ra[3] += r0.w;
            ra[4] += r1.x; ra[5] += r1.y; ra[6] += r1.z; ra[7] += r1.w;
        }
        // reduce over sp (lanes 4r..4r+3 adjacent)
        #pragma unroll
        for (int j = 0; j < 8; j++) {
            ea[j] += __shfl_xor_sync(0xffffffffu, ea[j], 1);
            ea[j] += __shfl_xor_sync(0xffffffffu, ea[j], 2);
            ra[j] += __shfl_xor_sync(0xffffffffu, ra[j], 1);
            ra[j] += __shfl_xor_sync(0xffffffffu, ra[j], 2);
        }
        if (sp == 0) {
            float iz = 1.f / ea[7];
            float dn = 1.f / fmaf(C01LN2, ra[7], 1.f);
            #pragma unroll
            for (int d = 0; d < 7; d++)
                c_s[row][d] = fmaf(ea[d], iz, C01LN2 * ra[d]) * dn;
            c_s[row][7] = 0.f;
        }
    }
    __syncthreads();

    // ---- phase 2: thread t -> float4-col j = t&63, rows rg*16..+16 ----
    const int j  = t & 63;
    const int rg = t >> 6;
    float4 wv4[7];
    #pragma unroll
    for (int d = 0; d < 7; d++)
        wv4[d] = ((const float4*)(Wv + (size_t)d * 256))[j];

    #pragma unroll 4
    for (int r = 0; r < 16; r++) {
        int row = rg * 16 + r;
        const float* c = c_s[row];
        float4 o;
        o.x = c[0] * wv4[0].x; o.y = c[0] * wv4[0].y;
        o.z = c[0] * wv4[0].z; o.w = c[0] * wv4[0].w;
        #pragma unroll
        for (int d = 1; d < 7; d++) {
            o.x = fmaf(c[d], wv4[d].x, o.x);
            o.y = fmaf(c[d], wv4[d].y, o.y);
            o.z = fmaf(c[d], wv4[d].z, o.z);
            o.w = fmaf(c[d], wv4[d].w, o.w);
        }
        ((float4*)(out + (size_t)(rbase + row) * 256))[j] = o;
    }
}

// ---------------------------------------------------------------------------
extern "C" void kernel_launch(void* const* d_in, const int* in_sizes, int n_in,
                              void* d_out, int out_size) {
    const float* x  = (const float*)d_in[0];
    const float* y  = (const float*)d_in[1];
    const float* Wq = (const float*)d_in[2];
    const float* Wk = (const float*)d_in[3];
    const float* Wv = (const float*)d_in[4];
    float* out = (float*)d_out;

    cudaFuncSetAttribute(attn_kernel, cudaFuncAttributeMaxDynamicSharedMemorySize,
                         ATT_SMEM);

    prep_kernel<<<160, 256>>>(y, Wq, Wk);
    qkp_kernel <<<128, 256>>>(x);
    attn_kernel<<<dim3(N_Q / 128, KSPLIT), 256, ATT_SMEM>>>();
    epi_kernel <<<256, 256>>>(Wv, out);
}